// round 1
// baseline (speedup 1.0000x reference)
#include <cuda_runtime.h>

#define NEDGE  300000
#define DNODE  128
#define DIN    384
#define DHID   256
#define DOUT   128
#define BM     64
#define NT     256

// smem row strides (floats), chosen so (4*stride) % 32 != 0 (bank spread) and % 4 == 0 (float4 align)
#define XSTR   388
#define HSTR   260
#define OSTR   132

#define SMEM_FLOATS (BM*XSTR + BM*HSTR + 32*DHID)
#define SMEM_BYTES  (SMEM_FLOATS * 4)

__global__ void __launch_bounds__(NT, 1)
edge_mlp_kernel(const float* __restrict__ node_attr,
                const float* __restrict__ edge_attr,
                const int*   __restrict__ eidx,
                const float* __restrict__ W1,
                const float* __restrict__ b1,
                const float* __restrict__ W2,
                const float* __restrict__ b2,
                const float* __restrict__ gamma_,
                const float* __restrict__ beta_,
                float*       __restrict__ out)
{
    extern __shared__ float smem[];
    float* Xs  = smem;                 // [BM][XSTR]  gathered input, row-major
    float* Hsm = smem + BM * XSTR;     // [BM][HSTR]  hidden
    float* Ws  = Hsm  + BM * HSTR;     // [32][256]   weight k-tile (reused for W2 [32][128])

    const int tid   = threadIdx.x;
    const int e0    = blockIdx.x * BM;
    const int nrows = min(BM, NEDGE - e0);

    // ---------------- gather: X[row][0:128)=sender, [128:256)=receiver, [256:384)=edge ----------
    for (int i = tid; i < BM * 96; i += NT) {
        int row = i / 96;
        int v   = i - row * 96;            // float4 index within the 384-wide row
        float4 val = make_float4(0.f, 0.f, 0.f, 0.f);
        if (row < nrows) {
            int e = e0 + row;
            if (v < 32) {
                int s = eidx[e];
                val = *reinterpret_cast<const float4*>(node_attr + (size_t)s * DNODE + v * 4);
            } else if (v < 64) {
                int r = eidx[NEDGE + e];
                val = *reinterpret_cast<const float4*>(node_attr + (size_t)r * DNODE + (v - 32) * 4);
            } else {
                val = *reinterpret_cast<const float4*>(edge_attr + (size_t)e * 128 + (v - 64) * 4);
            }
        }
        *reinterpret_cast<float4*>(Xs + row * XSTR + v * 4) = val;
    }

    const int tx = tid & 15;       // 16 column groups
    const int ty = tid >> 4;       // 16 row groups
    const int r0 = ty * 4;         // 4 consecutive rows per thread

    // ---------------- GEMM1: H[64,256] = relu(X[64,384] @ W1 + b1) ----------------
    float acc[4][16];
    #pragma unroll
    for (int a = 0; a < 4; a++)
        #pragma unroll
        for (int b = 0; b < 16; b++) acc[a][b] = 0.f;

    for (int kt = 0; kt < DIN; kt += 32) {
        __syncthreads();
        // load W1 k-tile [32][256]
        #pragma unroll
        for (int i = tid; i < 2048; i += NT) {
            int kk = i >> 6;
            int c4 = i & 63;
            *reinterpret_cast<float4*>(Ws + kk * DHID + c4 * 4) =
                *reinterpret_cast<const float4*>(W1 + (size_t)(kt + kk) * DHID + c4 * 4);
        }
        __syncthreads();

        #pragma unroll
        for (int kk = 0; kk < 32; kk += 4) {
            float x[4][4];
            #pragma unroll
            for (int r = 0; r < 4; r++) {
                float4 t = *reinterpret_cast<const float4*>(Xs + (r0 + r) * XSTR + kt + kk);
                x[r][0] = t.x; x[r][1] = t.y; x[r][2] = t.z; x[r][3] = t.w;
            }
            #pragma unroll
            for (int dk = 0; dk < 4; dk++) {
                float w[16];
                #pragma unroll
                for (int j = 0; j < 4; j++) {
                    float4 t = *reinterpret_cast<const float4*>(Ws + (kk + dk) * DHID + j * 64 + tx * 4);
                    w[j * 4 + 0] = t.x; w[j * 4 + 1] = t.y; w[j * 4 + 2] = t.z; w[j * 4 + 3] = t.w;
                }
                #pragma unroll
                for (int r = 0; r < 4; r++)
                    #pragma unroll
                    for (int c = 0; c < 16; c++)
                        acc[r][c] = fmaf(x[r][dk], w[c], acc[r][c]);
            }
        }
    }

    // bias + relu -> Hsm
    #pragma unroll
    for (int j = 0; j < 4; j++) {
        int cb = j * 64 + tx * 4;
        float4 bb = *reinterpret_cast<const float4*>(b1 + cb);
        #pragma unroll
        for (int r = 0; r < 4; r++) {
            float4 h;
            h.x = fmaxf(acc[r][j * 4 + 0] + bb.x, 0.f);
            h.y = fmaxf(acc[r][j * 4 + 1] + bb.y, 0.f);
            h.z = fmaxf(acc[r][j * 4 + 2] + bb.z, 0.f);
            h.w = fmaxf(acc[r][j * 4 + 3] + bb.w, 0.f);
            *reinterpret_cast<float4*>(Hsm + (r0 + r) * HSTR + cb) = h;
        }
    }

    // ---------------- GEMM2: O[64,128] = H @ W2 + b2 ----------------
    float acc2[4][8];
    #pragma unroll
    for (int a = 0; a < 4; a++)
        #pragma unroll
        for (int b = 0; b < 8; b++) acc2[a][b] = 0.f;

    for (int kt = 0; kt < DHID; kt += 32) {
        __syncthreads();   // Hsm written by all; previous Ws readers done
        // load W2 k-tile [32][128]
        #pragma unroll
        for (int i = tid; i < 1024; i += NT) {
            int kk = i >> 5;
            int c4 = i & 31;
            *reinterpret_cast<float4*>(Ws + kk * DOUT + c4 * 4) =
                *reinterpret_cast<const float4*>(W2 + (size_t)(kt + kk) * DOUT + c4 * 4);
        }
        __syncthreads();

        #pragma unroll
        for (int kk = 0; kk < 32; kk += 4) {
            float x[4][4];
            #pragma unroll
            for (int r = 0; r < 4; r++) {
                float4 t = *reinterpret_cast<const float4*>(Hsm + (r0 + r) * HSTR + kt + kk);
                x[r][0] = t.x; x[r][1] = t.y; x[r][2] = t.z; x[r][3] = t.w;
            }
            #pragma unroll
            for (int dk = 0; dk < 4; dk++) {
                float w[8];
                #pragma unroll
                for (int j = 0; j < 2; j++) {
                    float4 t = *reinterpret_cast<const float4*>(Ws + (kk + dk) * DOUT + j * 64 + tx * 4);
                    w[j * 4 + 0] = t.x; w[j * 4 + 1] = t.y; w[j * 4 + 2] = t.z; w[j * 4 + 3] = t.w;
                }
                #pragma unroll
                for (int r = 0; r < 4; r++)
                    #pragma unroll
                    for (int c = 0; c < 8; c++)
                        acc2[r][c] = fmaf(x[r][dk], w[c], acc2[r][c]);
            }
        }
    }

    // bias, stage O into smem (reuse Xs region) for row-wise LN
    float* Outs = Xs;   // [BM][OSTR]; safe: Xs is no longer read
    #pragma unroll
    for (int j = 0; j < 2; j++) {
        int cb = j * 64 + tx * 4;
        float4 bb = *reinterpret_cast<const float4*>(b2 + cb);
        #pragma unroll
        for (int r = 0; r < 4; r++) {
            float4 o;
            o.x = acc2[r][j * 4 + 0] + bb.x;
            o.y = acc2[r][j * 4 + 1] + bb.y;
            o.z = acc2[r][j * 4 + 2] + bb.z;
            o.w = acc2[r][j * 4 + 3] + bb.w;
            *reinterpret_cast<float4*>(Outs + (r0 + r) * OSTR + cb) = o;
        }
    }
    __syncthreads();

    // ---------------- LayerNorm per row (warp per row) ----------------
    const int lane = tid & 31;
    const int warp = tid >> 5;
    for (int row = warp; row < BM; row += 8) {
        float4 v = *reinterpret_cast<const float4*>(Outs + row * OSTR + lane * 4);
        float s = v.x + v.y + v.z + v.w;
        float q = v.x * v.x + v.y * v.y + v.z * v.z + v.w * v.w;
        #pragma unroll
        for (int o = 16; o > 0; o >>= 1) {
            s += __shfl_xor_sync(0xFFFFFFFFu, s, o);
            q += __shfl_xor_sync(0xFFFFFFFFu, q, o);
        }
        float mu  = s * (1.f / 128.f);
        float var = q * (1.f / 128.f) - mu * mu;
        float rs  = rsqrtf(var + 1e-5f);
        float4 g  = *reinterpret_cast<const float4*>(gamma_ + lane * 4);
        float4 be = *reinterpret_cast<const float4*>(beta_  + lane * 4);
        float4 o4;
        o4.x = (v.x - mu) * rs * g.x + be.x;
        o4.y = (v.y - mu) * rs * g.y + be.y;
        o4.z = (v.z - mu) * rs * g.z + be.z;
        o4.w = (v.w - mu) * rs * g.w + be.w;
        if (e0 + row < NEDGE)
            *reinterpret_cast<float4*>(out + (size_t)(e0 + row) * DOUT + lane * 4) = o4;
    }
}

extern "C" void kernel_launch(void* const* d_in, const int* in_sizes, int n_in,
                              void* d_out, int out_size)
{
    const float* node_attr = (const float*)d_in[0];
    const float* edge_attr = (const float*)d_in[1];
    const int*   eidx      = (const int*)  d_in[2];
    const float* W1        = (const float*)d_in[3];
    const float* b1        = (const float*)d_in[4];
    const float* W2        = (const float*)d_in[5];
    const float* b2        = (const float*)d_in[6];
    const float* gamma_    = (const float*)d_in[7];
    const float* beta_     = (const float*)d_in[8];
    float*       out       = (float*)d_out;

    cudaFuncSetAttribute(edge_mlp_kernel,
                         cudaFuncAttributeMaxDynamicSharedMemorySize, SMEM_BYTES);

    int grid = (NEDGE + BM - 1) / BM;   // 4688
    edge_mlp_kernel<<<grid, NT, SMEM_BYTES>>>(
        node_attr, edge_attr, eidx, W1, b1, W2, b2, gamma_, beta_, out);
}

// round 4
// speedup vs baseline: 2.3618x; 2.3618x over previous
#include <cuda_runtime.h>
#include <cuda_bf16.h>
#include <cstdint>

#define NEDGE  300000
#define DNODE  128
#define NT     256
#define BM     128

#define XSTRB  144          // bytes per bf16 row (72 bf16 = 64 data + 8 pad)
#define CH_B   18432        // 128 rows * 144
#define WCH1_B 36864        // 256 rows * 144

// ---- smem byte offsets (regions reused across phases, separated by syncs) ----
#define SM_XHI   0
#define SM_XLO   18432
#define SM_W1HI  36864
#define SM_W1LO  73728      // GEMM1 end: 110592
#define SM_HHI   0          // [4 chunks][128][144] = 73728
#define SM_HLO   73728      // 73728 .. 147456
#define SM_W2HI  147456
#define SM_W2LO  165888     // end 184320
#define SM_OUTS  0          // fp32 [128][132] after GEMM2
#define SM_TOTAL 184320

__device__ __align__(16) unsigned short g_W1t_hi[6 * 256 * 72];
__device__ __align__(16) unsigned short g_W1t_lo[6 * 256 * 72];
__device__ __align__(16) unsigned short g_W2t_hi[4 * 128 * 72];
__device__ __align__(16) unsigned short g_W2t_lo[4 * 128 * 72];

__device__ __forceinline__ uint32_t smem_u32(const void* p) {
    uint32_t a;
    asm("{ .reg .u64 t; cvta.to.shared.u64 t, %1; cvt.u32.u64 %0, t; }" : "=r"(a) : "l"(p));
    return a;
}

#define LDSM_X4(r, a) \
    asm volatile("ldmatrix.sync.aligned.m8n8.x4.shared.b16 {%0,%1,%2,%3}, [%4];" \
        : "=r"((r)[0]), "=r"((r)[1]), "=r"((r)[2]), "=r"((r)[3]) : "r"(a))

#define MMA16816(d, a, b0r, b1r) \
    asm volatile("mma.sync.aligned.m16n8k16.row.col.f32.bf16.bf16.f32 " \
        "{%0,%1,%2,%3}, {%4,%5,%6,%7}, {%8,%9}, {%0,%1,%2,%3};" \
        : "+f"((d)[0]), "+f"((d)[1]), "+f"((d)[2]), "+f"((d)[3]) \
        : "r"((a)[0]), "r"((a)[1]), "r"((a)[2]), "r"((a)[3]), "r"(b0r), "r"(b1r))

__device__ __forceinline__ void split_pack8(const float* f, uint4* hi, uint4* lo) {
    unsigned short hs[8], ls[8];
    #pragma unroll
    for (int j = 0; j < 8; j++) {
        __nv_bfloat16 b = __float2bfloat16_rn(f[j]);
        float r = f[j] - __bfloat162float(b);
        hs[j] = __bfloat16_as_ushort(b);
        ls[j] = __bfloat16_as_ushort(__float2bfloat16_rn(r));
    }
    hi->x = (uint32_t)hs[0] | ((uint32_t)hs[1] << 16);
    hi->y = (uint32_t)hs[2] | ((uint32_t)hs[3] << 16);
    hi->z = (uint32_t)hs[4] | ((uint32_t)hs[5] << 16);
    hi->w = (uint32_t)hs[6] | ((uint32_t)hs[7] << 16);
    lo->x = (uint32_t)ls[0] | ((uint32_t)ls[1] << 16);
    lo->y = (uint32_t)ls[2] | ((uint32_t)ls[3] << 16);
    lo->z = (uint32_t)ls[4] | ((uint32_t)ls[5] << 16);
    lo->w = (uint32_t)ls[6] | ((uint32_t)ls[7] << 16);
}

__device__ __forceinline__ uint32_t pack_hi2(float v0, float v1, uint32_t* lo) {
    __nv_bfloat16 h0 = __float2bfloat16_rn(v0);
    __nv_bfloat16 h1 = __float2bfloat16_rn(v1);
    float r0 = v0 - __bfloat162float(h0);
    float r1 = v1 - __bfloat162float(h1);
    *lo = (uint32_t)__bfloat16_as_ushort(__float2bfloat16_rn(r0))
        | ((uint32_t)__bfloat16_as_ushort(__float2bfloat16_rn(r1)) << 16);
    return (uint32_t)__bfloat16_as_ushort(h0)
         | ((uint32_t)__bfloat16_as_ushort(h1) << 16);
}

// Split weights into bf16 hi/lo, transposed [N][K] with 72-element padded rows.
__global__ void prep_weights(const float* __restrict__ W1, const float* __restrict__ W2) {
    int idx = blockIdx.x * blockDim.x + threadIdx.x;
    if (idx < 384 * 256) {
        int k = idx >> 8, n = idx & 255;
        float v = W1[idx];
        __nv_bfloat16 h = __float2bfloat16_rn(v);
        float r = v - __bfloat162float(h);
        int c = k >> 6, kin = k & 63;
        int o = (c * 256 + n) * 72 + kin;
        g_W1t_hi[o] = __bfloat16_as_ushort(h);
        g_W1t_lo[o] = __bfloat16_as_ushort(__float2bfloat16_rn(r));
    }
    if (idx < 256 * 128) {
        int k = idx >> 7, n = idx & 127;
        float v = W2[idx];
        __nv_bfloat16 h = __float2bfloat16_rn(v);
        float r = v - __bfloat162float(h);
        int c = k >> 6, kin = k & 63;
        int o = (c * 128 + n) * 72 + kin;
        g_W2t_hi[o] = __bfloat16_as_ushort(h);
        g_W2t_lo[o] = __bfloat16_as_ushort(__float2bfloat16_rn(r));
    }
}

__global__ void __launch_bounds__(NT, 1)
edge_mlp_mma(const float* __restrict__ node_attr,
             const float* __restrict__ edge_attr,
             const int*   __restrict__ eidx,
             const float* __restrict__ b1,
             const float* __restrict__ b2,
             const float* __restrict__ gamma_,
             const float* __restrict__ beta_,
             float*       __restrict__ out)
{
    extern __shared__ __align__(16) char smem[];
    const uint32_t sb = smem_u32(smem);

    const int tid  = threadIdx.x;
    const int lane = tid & 31;
    const int wid  = tid >> 5;
    const int e0   = blockIdx.x * BM;
    const int nrows = min(BM, NEDGE - e0);

    // ldmatrix per-lane address pattern for 16x16 b16 tiles
    const int lr  = (lane & 7) + ((lane >> 3) & 1) * 8;   // row within 16
    const int lcb = (lane >> 4) * 16;                      // byte col (0|16)

    const int m0 = (wid >> 2) * 64;
    const int nw = (wid & 3);
    const int n0 = nw * 64;

    const int grow  = tid >> 1;
    const int ghalf = tid & 1;

    // ================= GEMM1 =================
    float acc[4][8][4];
    #pragma unroll
    for (int a = 0; a < 4; a++)
        #pragma unroll
        for (int b = 0; b < 8; b++)
            #pragma unroll
            for (int j = 0; j < 4; j++) acc[a][b][j] = 0.f;

    for (int c = 0; c < 6; c++) {
        __syncthreads();
        // gather + split X chunk [128][64]
        const float* src = nullptr;
        if (grow < nrows) {
            int e = e0 + grow;
            if (c < 2)      src = node_attr + (size_t)__ldg(&eidx[e]) * DNODE + c * 64;
            else if (c < 4) src = node_attr + (size_t)__ldg(&eidx[NEDGE + e]) * DNODE + (c - 2) * 64;
            else            src = edge_attr + (size_t)e * DNODE + (c - 4) * 64;
        }
        #pragma unroll
        for (int g = 0; g < 4; g++) {
            float f[8];
            if (src) {
                float4 a4 = *(const float4*)(src + ghalf * 32 + g * 8);
                float4 b4 = *(const float4*)(src + ghalf * 32 + g * 8 + 4);
                f[0] = a4.x; f[1] = a4.y; f[2] = a4.z; f[3] = a4.w;
                f[4] = b4.x; f[5] = b4.y; f[6] = b4.z; f[7] = b4.w;
            } else {
                #pragma unroll
                for (int j = 0; j < 8; j++) f[j] = 0.f;
            }
            uint4 hi, lo;
            split_pack8(f, &hi, &lo);
            uint32_t off = grow * XSTRB + ghalf * 64 + g * 16;
            *(uint4*)(smem + SM_XHI + off) = hi;
            *(uint4*)(smem + SM_XLO + off) = lo;
        }
        // copy W1 chunk (hi/lo), 2304 uint4 each
        {
            const uint4* wh = (const uint4*)g_W1t_hi + c * 2304;
            const uint4* wl = (const uint4*)g_W1t_lo + c * 2304;
            uint4* dh = (uint4*)(smem + SM_W1HI);
            uint4* dl = (uint4*)(smem + SM_W1LO);
            #pragma unroll
            for (int i = 0; i < 9; i++) {
                dh[tid + i * 256] = wh[tid + i * 256];
                dl[tid + i * 256] = wl[tid + i * 256];
            }
        }
        __syncthreads();

        const uint32_t aHi = sb + SM_XHI  + (uint32_t)(m0 + lr) * XSTRB + lcb;
        const uint32_t aLo = sb + SM_XLO  + (uint32_t)(m0 + lr) * XSTRB + lcb;
        const uint32_t bHi = sb + SM_W1HI + (uint32_t)(n0 + lr) * XSTRB + lcb;
        const uint32_t bLo = sb + SM_W1LO + (uint32_t)(n0 + lr) * XSTRB + lcb;

        #pragma unroll
        for (int ks = 0; ks < 4; ks++) {
            const int kb = ks * 32;
            uint32_t Ah[4][4], Bh[4][4];
            #pragma unroll
            for (int mt = 0; mt < 4; mt++) LDSM_X4(Ah[mt], aHi + mt * 16 * XSTRB + kb);
            #pragma unroll
            for (int np = 0; np < 4; np++) LDSM_X4(Bh[np], bHi + np * 16 * XSTRB + kb);
            #pragma unroll
            for (int mt = 0; mt < 4; mt++)
                #pragma unroll
                for (int nt = 0; nt < 8; nt++)
                    MMA16816(acc[mt][nt], Ah[mt], Bh[nt >> 1][nt & 1], Bh[nt >> 1][2 + (nt & 1)]);
            {
                uint32_t Al[4][4];
                #pragma unroll
                for (int mt = 0; mt < 4; mt++) LDSM_X4(Al[mt], aLo + mt * 16 * XSTRB + kb);
                #pragma unroll
                for (int mt = 0; mt < 4; mt++)
                    #pragma unroll
                    for (int nt = 0; nt < 8; nt++)
                        MMA16816(acc[mt][nt], Al[mt], Bh[nt >> 1][nt & 1], Bh[nt >> 1][2 + (nt & 1)]);
            }
            {
                uint32_t Bl[4][4];
                #pragma unroll
                for (int np = 0; np < 4; np++) LDSM_X4(Bl[np], bLo + np * 16 * XSTRB + kb);
                #pragma unroll
                for (int mt = 0; mt < 4; mt++)
                    #pragma unroll
                    for (int nt = 0; nt < 8; nt++)
                        MMA16816(acc[mt][nt], Ah[mt], Bl[nt >> 1][nt & 1], Bl[nt >> 1][2 + (nt & 1)]);
            }
        }
    }
    __syncthreads();   // all ldmatrix reads done; H overlays X/W1 regions

    // ================= Epilogue1: H = relu(acc + b1), split to bf16 hi/lo =================
    {
        const int qr = lane >> 2;
        const int qc = (lane & 3) * 2;
        #pragma unroll
        for (int mt = 0; mt < 4; mt++) {
            const int r0 = m0 + mt * 16 + qr;
            #pragma unroll
            for (int nt = 0; nt < 8; nt++) {
                const int kin = nt * 8 + qc;
                float2 bb = *(const float2*)(b1 + n0 + kin);
                float v0 = fmaxf(acc[mt][nt][0] + bb.x, 0.f);
                float v1 = fmaxf(acc[mt][nt][1] + bb.y, 0.f);
                float v2 = fmaxf(acc[mt][nt][2] + bb.x, 0.f);
                float v3 = fmaxf(acc[mt][nt][3] + bb.y, 0.f);
                uint32_t l01, l23;
                uint32_t h01 = pack_hi2(v0, v1, &l01);
                uint32_t h23 = pack_hi2(v2, v3, &l23);
                uint32_t base = nw * CH_B + (uint32_t)r0 * XSTRB + kin * 2;
                *(uint32_t*)(smem + SM_HHI + base)                = h01;
                *(uint32_t*)(smem + SM_HLO + base)                = l01;
                *(uint32_t*)(smem + SM_HHI + base + 8 * XSTRB)    = h23;
                *(uint32_t*)(smem + SM_HLO + base + 8 * XSTRB)    = l23;
            }
        }
    }

    // ================= GEMM2 =================
    const int n0b = (wid & 3) * 32;
    float acc2[4][4][4];
    #pragma unroll
    for (int a = 0; a < 4; a++)
        #pragma unroll
        for (int b = 0; b < 4; b++)
            #pragma unroll
            for (int j = 0; j < 4; j++) acc2[a][b][j] = 0.f;

    for (int c = 0; c < 4; c++) {
        __syncthreads();
        // copy W2 chunk (hi/lo), 1152 uint4 each
        {
            const uint4* wh = (const uint4*)g_W2t_hi + c * 1152;
            const uint4* wl = (const uint4*)g_W2t_lo + c * 1152;
            uint4* dh = (uint4*)(smem + SM_W2HI);
            uint4* dl = (uint4*)(smem + SM_W2LO);
            for (int i = tid; i < 1152; i += NT) {
                dh[i] = wh[i];
                dl[i] = wl[i];
            }
        }
        __syncthreads();

        const uint32_t aHi = sb + SM_HHI + c * CH_B + (uint32_t)(m0 + lr) * XSTRB + lcb;
        const uint32_t aLo = sb + SM_HLO + c * CH_B + (uint32_t)(m0 + lr) * XSTRB + lcb;
        const uint32_t bHi = sb + SM_W2HI + (uint32_t)(n0b + lr) * XSTRB + lcb;
        const uint32_t bLo = sb + SM_W2LO + (uint32_t)(n0b + lr) * XSTRB + lcb;

        #pragma unroll
        for (int ks = 0; ks < 4; ks++) {
            const int kb = ks * 32;
            uint32_t Ah[4][4], Bh[2][4];
            #pragma unroll
            for (int mt = 0; mt < 4; mt++) LDSM_X4(Ah[mt], aHi + mt * 16 * XSTRB + kb);
            #pragma unroll
            for (int np = 0; np < 2; np++) LDSM_X4(Bh[np], bHi + np * 16 * XSTRB + kb);
            #pragma unroll
            for (int mt = 0; mt < 4; mt++)
                #pragma unroll
                for (int nt = 0; nt < 4; nt++)
                    MMA16816(acc2[mt][nt], Ah[mt], Bh[nt >> 1][nt & 1], Bh[nt >> 1][2 + (nt & 1)]);
            {
                uint32_t Al[4][4];
                #pragma unroll
                for (int mt = 0; mt < 4; mt++) LDSM_X4(Al[mt], aLo + mt * 16 * XSTRB + kb);
                #pragma unroll
                for (int mt = 0; mt < 4; mt++)
                    #pragma unroll
                    for (int nt = 0; nt < 4; nt++)
                        MMA16816(acc2[mt][nt], Al[mt], Bh[nt >> 1][nt & 1], Bh[nt >> 1][2 + (nt & 1)]);
            }
            {
                uint32_t Bl[2][4];
                #pragma unroll
                for (int np = 0; np < 2; np++) LDSM_X4(Bl[np], bLo + np * 16 * XSTRB + kb);
                #pragma unroll
                for (int mt = 0; mt < 4; mt++)
                    #pragma unroll
                    for (int nt = 0; nt < 4; nt++)
                        MMA16816(acc2[mt][nt], Ah[mt], Bl[nt >> 1][nt & 1], Bl[nt >> 1][2 + (nt & 1)]);
            }
        }
    }
    __syncthreads();   // all H reads done; Outs overlays H

    // ================= Epilogue2: stage O = acc2 + b2 =================
    float* Outs = (float*)(smem + SM_OUTS);   // [128][132] fp32
    {
        const int qr = lane >> 2;
        const int qc = (lane & 3) * 2;
        #pragma unroll
        for (int mt = 0; mt < 4; mt++) {
            const int r0 = m0 + mt * 16 + qr;
            #pragma unroll
            for (int nt = 0; nt < 4; nt++) {
                const int cc = n0b + nt * 8 + qc;
                float2 bb = *(const float2*)(b2 + cc);
                float2 o01 = make_float2(acc2[mt][nt][0] + bb.x, acc2[mt][nt][1] + bb.y);
                float2 o23 = make_float2(acc2[mt][nt][2] + bb.x, acc2[mt][nt][3] + bb.y);
                *(float2*)(Outs + (size_t)r0 * 132 + cc)       = o01;
                *(float2*)(Outs + (size_t)(r0 + 8) * 132 + cc) = o23;
            }
        }
    }
    __syncthreads();

    // ================= LayerNorm + store (warp per row) =================
    for (int row = wid; row < BM; row += 8) {
        float4 v = *(const float4*)(Outs + (size_t)row * 132 + lane * 4);
        float s = v.x + v.y + v.z + v.w;
        float q = v.x * v.x + v.y * v.y + v.z * v.z + v.w * v.w;
        #pragma unroll
        for (int o = 16; o > 0; o >>= 1) {
            s += __shfl_xor_sync(0xFFFFFFFFu, s, o);
            q += __shfl_xor_sync(0xFFFFFFFFu, q, o);
        }
        float mu  = s * (1.f / 128.f);
        float var = q * (1.f / 128.f) - mu * mu;
        float rs  = rsqrtf(var + 1e-5f);
        float4 g  = *(const float4*)(gamma_ + lane * 4);
        float4 be = *(const float4*)(beta_  + lane * 4);
        float4 o4;
        o4.x = (v.x - mu) * rs * g.x + be.x;
        o4.y = (v.y - mu) * rs * g.y + be.y;
        o4.z = (v.z - mu) * rs * g.z + be.z;
        o4.w = (v.w - mu) * rs * g.w + be.w;
        if (e0 + row < NEDGE)
            *(float4*)(out + (size_t)(e0 + row) * 128 + lane * 4) = o4;
    }
}

extern "C" void kernel_launch(void* const* d_in, const int* in_sizes, int n_in,
                              void* d_out, int out_size)
{
    const float* node_attr = (const float*)d_in[0];
    const float* edge_attr = (const float*)d_in[1];
    const int*   eidx      = (const int*)  d_in[2];
    const float* W1        = (const float*)d_in[3];
    const float* b1        = (const float*)d_in[4];
    const float* W2        = (const float*)d_in[5];
    const float* b2        = (const float*)d_in[6];
    const float* gamma_    = (const float*)d_in[7];
    const float* beta_     = (const float*)d_in[8];
    float*       out       = (float*)d_out;

    prep_weights<<<(384 * 256 + 255) / 256, 256>>>(W1, W2);

    cudaFuncSetAttribute(edge_mlp_mma,
                         cudaFuncAttributeMaxDynamicSharedMemorySize, SM_TOTAL);
    int grid = (NEDGE + BM - 1) / BM;   // 2344
    edge_mlp_mma<<<grid, NT, SM_TOTAL>>>(
        node_attr, edge_attr, eidx, b1, b2, gamma_, beta_, out);
}

// round 6
// speedup vs baseline: 2.6018x; 1.1016x over previous
#include <cuda_runtime.h>
#include <cuda_bf16.h>
#include <cstdint>

#define NEDGE  300000
#define DNODE  128
#define NT     256
#define BM     128

#define XSTRB  144          // bytes per bf16 row (72 bf16 = 64 data + 8 pad)

// ---- smem byte offsets ----
// GEMM1 phase: Xbuf[2] @ 0/36864 (hi +0, lo +18432), W1buf[2] @ 73728/147456 (hi +0, lo +36864)
// GEMM2 phase: W2buf[2] @ 0/36864 (hi +0, lo +18432), H hi @ 73728 (+c*18432), H lo @ 147456 (+c*18432)
// LN phase:    Outs fp32 [128][132] @ 0
#define SM_XBUF   0
#define SM_XSTRIDE 36864
#define SM_XLO_OFF 18432
#define SM_W1BUF  73728
#define SM_W1STRIDE 73728
#define SM_W1LO_OFF 36864
#define SM_W2BUF  0
#define SM_W2STRIDE 36864
#define SM_W2LO_OFF 18432
#define SM_HHI    73728
#define SM_HLO    147456
#define SM_HSTRIDE 18432
#define SM_OUTS   0
#define SM_TOTAL  221184

__device__ __align__(16) unsigned short g_W1t_hi[6 * 256 * 72];
__device__ __align__(16) unsigned short g_W1t_lo[6 * 256 * 72];
__device__ __align__(16) unsigned short g_W2t_hi[4 * 128 * 72];
__device__ __align__(16) unsigned short g_W2t_lo[4 * 128 * 72];

__device__ __forceinline__ uint32_t smem_u32(const void* p) {
    uint32_t a;
    asm("{ .reg .u64 t; cvta.to.shared.u64 t, %1; cvt.u32.u64 %0, t; }" : "=r"(a) : "l"(p));
    return a;
}

#define LDSM_X4(r, a) \
    asm volatile("ldmatrix.sync.aligned.m8n8.x4.shared.b16 {%0,%1,%2,%3}, [%4];" \
        : "=r"((r)[0]), "=r"((r)[1]), "=r"((r)[2]), "=r"((r)[3]) : "r"(a))

#define MMA16816(d, a, b0r, b1r) \
    asm volatile("mma.sync.aligned.m16n8k16.row.col.f32.bf16.bf16.f32 " \
        "{%0,%1,%2,%3}, {%4,%5,%6,%7}, {%8,%9}, {%0,%1,%2,%3};" \
        : "+f"((d)[0]), "+f"((d)[1]), "+f"((d)[2]), "+f"((d)[3]) \
        : "r"((a)[0]), "r"((a)[1]), "r"((a)[2]), "r"((a)[3]), "r"(b0r), "r"(b1r))

#define CP16(dst, src) \
    asm volatile("cp.async.cg.shared.global [%0], [%1], 16;" :: "r"(dst), "l"(src) : "memory")
#define CP_COMMIT() asm volatile("cp.async.commit_group;" ::: "memory")
#define CP_WAIT0()  asm volatile("cp.async.wait_group 0;" ::: "memory")

__device__ __forceinline__ void split_pack8(const float* f, uint4* hi, uint4* lo) {
    unsigned short hs[8], ls[8];
    #pragma unroll
    for (int j = 0; j < 8; j++) {
        __nv_bfloat16 b = __float2bfloat16_rn(f[j]);
        float r = f[j] - __bfloat162float(b);
        hs[j] = __bfloat16_as_ushort(b);
        ls[j] = __bfloat16_as_ushort(__float2bfloat16_rn(r));
    }
    hi->x = (uint32_t)hs[0] | ((uint32_t)hs[1] << 16);
    hi->y = (uint32_t)hs[2] | ((uint32_t)hs[3] << 16);
    hi->z = (uint32_t)hs[4] | ((uint32_t)hs[5] << 16);
    hi->w = (uint32_t)hs[6] | ((uint32_t)hs[7] << 16);
    lo->x = (uint32_t)ls[0] | ((uint32_t)ls[1] << 16);
    lo->y = (uint32_t)ls[2] | ((uint32_t)ls[3] << 16);
    lo->z = (uint32_t)ls[4] | ((uint32_t)ls[5] << 16);
    lo->w = (uint32_t)ls[6] | ((uint32_t)ls[7] << 16);
}

__device__ __forceinline__ uint32_t pack_hi2(float v0, float v1, uint32_t* lo) {
    __nv_bfloat16 h0 = __float2bfloat16_rn(v0);
    __nv_bfloat16 h1 = __float2bfloat16_rn(v1);
    float r0 = v0 - __bfloat162float(h0);
    float r1 = v1 - __bfloat162float(h1);
    *lo = (uint32_t)__bfloat16_as_ushort(__float2bfloat16_rn(r0))
        | ((uint32_t)__bfloat16_as_ushort(__float2bfloat16_rn(r1)) << 16);
    return (uint32_t)__bfloat16_as_ushort(h0)
         | ((uint32_t)__bfloat16_as_ushort(h1) << 16);
}

__global__ void prep_weights(const float* __restrict__ W1, const float* __restrict__ W2) {
    int idx = blockIdx.x * blockDim.x + threadIdx.x;
    if (idx < 384 * 256) {
        int k = idx >> 8, n = idx & 255;
        float v = W1[idx];
        __nv_bfloat16 h = __float2bfloat16_rn(v);
        float r = v - __bfloat162float(h);
        int c = k >> 6, kin = k & 63;
        int o = (c * 256 + n) * 72 + kin;
        g_W1t_hi[o] = __bfloat16_as_ushort(h);
        g_W1t_lo[o] = __bfloat16_as_ushort(__float2bfloat16_rn(r));
    }
    if (idx < 256 * 128) {
        int k = idx >> 7, n = idx & 127;
        float v = W2[idx];
        __nv_bfloat16 h = __float2bfloat16_rn(v);
        float r = v - __bfloat162float(h);
        int c = k >> 6, kin = k & 63;
        int o = (c * 128 + n) * 72 + kin;
        g_W2t_hi[o] = __bfloat16_as_ushort(h);
        g_W2t_lo[o] = __bfloat16_as_ushort(__float2bfloat16_rn(r));
    }
}

__global__ void __launch_bounds__(NT, 1)
edge_mlp_mma(const float* __restrict__ node_attr,
             const float* __restrict__ edge_attr,
             const int*   __restrict__ eidx,
             const float* __restrict__ b1,
             const float* __restrict__ b2,
             const float* __restrict__ gamma_,
             const float* __restrict__ beta_,
             float*       __restrict__ out)
{
    extern __shared__ __align__(16) char smem[];
    const uint32_t sb = smem_u32(smem);

    const int tid  = threadIdx.x;
    const int lane = tid & 31;
    const int wid  = tid >> 5;
    const int e0   = blockIdx.x * BM;
    const int nrows = min(BM, NEDGE - e0);

    const int lr  = (lane & 7) + ((lane >> 3) & 1) * 8;
    const int lcb = (lane >> 4) * 16;

    const int m0 = (wid >> 2) * 64;
    const int nw = (wid & 3);
    const int n0 = nw * 64;

    const int grow  = tid >> 1;
    const int ghalf = tid & 1;

    // per-thread gather indices, loaded once
    int sidx = 0, ridx = 0;
    const bool gvalid = (grow < nrows);
    if (gvalid) {
        sidx = __ldg(&eidx[e0 + grow]);
        ridx = __ldg(&eidx[NEDGE + e0 + grow]);
    }

    // ---- helpers as macros over locals ----
    #define GATHER_X(c, xbase) do { \
        const float* _src = nullptr; \
        if (gvalid) { \
            if ((c) < 2)      _src = node_attr + (size_t)sidx * DNODE + (c) * 64; \
            else if ((c) < 4) _src = node_attr + (size_t)ridx * DNODE + ((c) - 2) * 64; \
            else              _src = edge_attr + (size_t)(e0 + grow) * DNODE + ((c) - 4) * 64; \
        } \
        _Pragma("unroll") \
        for (int _g = 0; _g < 4; _g++) { \
            float _f[8]; \
            if (_src) { \
                float4 _a4 = *(const float4*)(_src + ghalf * 32 + _g * 8); \
                float4 _b4 = *(const float4*)(_src + ghalf * 32 + _g * 8 + 4); \
                _f[0] = _a4.x; _f[1] = _a4.y; _f[2] = _a4.z; _f[3] = _a4.w; \
                _f[4] = _b4.x; _f[5] = _b4.y; _f[6] = _b4.z; _f[7] = _b4.w; \
            } else { \
                _Pragma("unroll") for (int _j = 0; _j < 8; _j++) _f[_j] = 0.f; \
            } \
            uint4 _hi, _lo; \
            split_pack8(_f, &_hi, &_lo); \
            uint32_t _off = (xbase) + grow * XSTRB + ghalf * 64 + _g * 16; \
            *(uint4*)(smem + _off)              = _hi; \
            *(uint4*)(smem + _off + SM_XLO_OFF) = _lo; \
        } \
    } while (0)

    #define CP_W1(c, wbase) do { \
        const char* _wh = (const char*)g_W1t_hi + (c) * 36864; \
        const char* _wl = (const char*)g_W1t_lo + (c) * 36864; \
        uint32_t _dh = sb + (wbase); \
        uint32_t _dl = sb + (wbase) + SM_W1LO_OFF; \
        _Pragma("unroll") \
        for (int _i = 0; _i < 9; _i++) { \
            uint32_t _o = (uint32_t)(tid + _i * 256) * 16; \
            CP16(_dh + _o, _wh + _o); \
            CP16(_dl + _o, _wl + _o); \
        } \
    } while (0)

    #define CP_W2(c, wbase) do { \
        const char* _wh = (const char*)g_W2t_hi + (c) * 18432; \
        const char* _wl = (const char*)g_W2t_lo + (c) * 18432; \
        uint32_t _dh = sb + (wbase); \
        uint32_t _dl = sb + (wbase) + SM_W2LO_OFF; \
        _Pragma("unroll") \
        for (int _i = 0; _i < 5; _i++) { \
            int _idx = tid + _i * 256; \
            if (_idx < 1152) { \
                uint32_t _o = (uint32_t)_idx * 16; \
                CP16(_dh + _o, _wh + _o); \
                CP16(_dl + _o, _wl + _o); \
            } \
        } \
    } while (0)

    // ================= GEMM1 (pipelined) =================
    float acc[4][8][4];
    #pragma unroll
    for (int a = 0; a < 4; a++)
        #pragma unroll
        for (int b = 0; b < 8; b++)
            #pragma unroll
            for (int j = 0; j < 4; j++) acc[a][b][j] = 0.f;

    // prologue: chunk 0
    CP_W1(0, SM_W1BUF);
    CP_COMMIT();
    GATHER_X(0, SM_XBUF);
    CP_WAIT0();
    __syncthreads();

    for (int c = 0; c < 6; c++) {
        const int nb = (c + 1) & 1;
        if (c < 5) {
            CP_W1(c + 1, SM_W1BUF + nb * SM_W1STRIDE);
            CP_COMMIT();
            GATHER_X(c + 1, SM_XBUF + nb * SM_XSTRIDE);
        } else {
            CP_W2(0, SM_W2BUF);   // prefetch W2 chunk 0 into free Xbuf0 region
            CP_COMMIT();
        }

        const uint32_t xb = SM_XBUF + (uint32_t)(c & 1) * SM_XSTRIDE;
        const uint32_t wb = SM_W1BUF + (uint32_t)(c & 1) * SM_W1STRIDE;
        const uint32_t aHi = sb + xb + (uint32_t)(m0 + lr) * XSTRB + lcb;
        const uint32_t aLo = aHi + SM_XLO_OFF;
        const uint32_t bHi = sb + wb + (uint32_t)(n0 + lr) * XSTRB + lcb;
        const uint32_t bLo = bHi + SM_W1LO_OFF;

        #pragma unroll
        for (int ks = 0; ks < 4; ks++) {
            const int kb = ks * 32;
            uint32_t Ah[4][4], Bh[4][4];
            #pragma unroll
            for (int mt = 0; mt < 4; mt++) LDSM_X4(Ah[mt], aHi + mt * 16 * XSTRB + kb);
            #pragma unroll
            for (int np = 0; np < 4; np++) LDSM_X4(Bh[np], bHi + np * 16 * XSTRB + kb);
            #pragma unroll
            for (int mt = 0; mt < 4; mt++)
                #pragma unroll
                for (int nt = 0; nt < 8; nt++)
                    MMA16816(acc[mt][nt], Ah[mt], Bh[nt >> 1][nt & 1], Bh[nt >> 1][2 + (nt & 1)]);
            {
                uint32_t Al[4][4];
                #pragma unroll
                for (int mt = 0; mt < 4; mt++) LDSM_X4(Al[mt], aLo + mt * 16 * XSTRB + kb);
                #pragma unroll
                for (int mt = 0; mt < 4; mt++)
                    #pragma unroll
                    for (int nt = 0; nt < 8; nt++)
                        MMA16816(acc[mt][nt], Al[mt], Bh[nt >> 1][nt & 1], Bh[nt >> 1][2 + (nt & 1)]);
            }
            {
                uint32_t Bl[4][4];
                #pragma unroll
                for (int np = 0; np < 4; np++) LDSM_X4(Bl[np], bLo + np * 16 * XSTRB + kb);
                #pragma unroll
                for (int mt = 0; mt < 4; mt++)
                    #pragma unroll
                    for (int nt = 0; nt < 8; nt++)
                        MMA16816(acc[mt][nt], Ah[mt], Bl[nt >> 1][nt & 1], Bl[nt >> 1][2 + (nt & 1)]);
            }
        }
        CP_WAIT0();
        __syncthreads();
    }

    // ================= Epilogue1: H = relu(acc + b1) -> bf16 hi/lo chunks =================
    {
        const int qr = lane >> 2;
        const int qc = (lane & 3) * 2;
        #pragma unroll
        for (int mt = 0; mt < 4; mt++) {
            const int r0 = m0 + mt * 16 + qr;
            #pragma unroll
            for (int nt = 0; nt < 8; nt++) {
                const int kin = nt * 8 + qc;
                float2 bb = *(const float2*)(b1 + n0 + kin);
                float v0 = fmaxf(acc[mt][nt][0] + bb.x, 0.f);
                float v1 = fmaxf(acc[mt][nt][1] + bb.y, 0.f);
                float v2 = fmaxf(acc[mt][nt][2] + bb.x, 0.f);
                float v3 = fmaxf(acc[mt][nt][3] + bb.y, 0.f);
                uint32_t l01, l23;
                uint32_t h01 = pack_hi2(v0, v1, &l01);
                uint32_t h23 = pack_hi2(v2, v3, &l23);
                uint32_t boff = (uint32_t)nw * SM_HSTRIDE + (uint32_t)r0 * XSTRB + kin * 2;
                *(uint32_t*)(smem + SM_HHI + boff)             = h01;
                *(uint32_t*)(smem + SM_HLO + boff)             = l01;
                *(uint32_t*)(smem + SM_HHI + boff + 8 * XSTRB) = h23;
                *(uint32_t*)(smem + SM_HLO + boff + 8 * XSTRB) = l23;
            }
        }
    }
    __syncthreads();

    // ================= GEMM2 (pipelined) =================
    const int n0b = (wid & 3) * 32;
    float acc2[4][4][4];
    #pragma unroll
    for (int a = 0; a < 4; a++)
        #pragma unroll
        for (int b = 0; b < 4; b++)
            #pragma unroll
            for (int j = 0; j < 4; j++) acc2[a][b][j] = 0.f;

    for (int c = 0; c < 4; c++) {
        const int nb = (c + 1) & 1;
        if (c < 3) {
            CP_W2(c + 1, SM_W2BUF + nb * SM_W2STRIDE);
            CP_COMMIT();
        }

        const uint32_t aHi = sb + SM_HHI + (uint32_t)c * SM_HSTRIDE + (uint32_t)(m0 + lr) * XSTRB + lcb;
        const uint32_t aLo = sb + SM_HLO + (uint32_t)c * SM_HSTRIDE + (uint32_t)(m0 + lr) * XSTRB + lcb;
        const uint32_t bHi = sb + SM_W2BUF + (uint32_t)(c & 1) * SM_W2STRIDE + (uint32_t)(n0b + lr) * XSTRB + lcb;
        const uint32_t bLo = bHi + SM_W2LO_OFF;

        #pragma unroll
        for (int ks = 0; ks < 4; ks++) {
            const int kb = ks * 32;
            uint32_t Ah[4][4], Bh[2][4];
            #pragma unroll
            for (int mt = 0; mt < 4; mt++) LDSM_X4(Ah[mt], aHi + mt * 16 * XSTRB + kb);
            #pragma unroll
            for (int np = 0; np < 2; np++) LDSM_X4(Bh[np], bHi + np * 16 * XSTRB + kb);
            #pragma unroll
            for (int mt = 0; mt < 4; mt++)
                #pragma unroll
                for (int nt = 0; nt < 4; nt++)
                    MMA16816(acc2[mt][nt], Ah[mt], Bh[nt >> 1][nt & 1], Bh[nt >> 1][2 + (nt & 1)]);
            {
                uint32_t Al[4][4];
                #pragma unroll
                for (int mt = 0; mt < 4; mt++) LDSM_X4(Al[mt], aLo + mt * 16 * XSTRB + kb);
                #pragma unroll
                for (int mt = 0; mt < 4; mt++)
                    #pragma unroll
                    for (int nt = 0; nt < 4; nt++)
                        MMA16816(acc2[mt][nt], Al[mt], Bh[nt >> 1][nt & 1], Bh[nt >> 1][2 + (nt & 1)]);
            }
            {
                uint32_t Bl[2][4];
                #pragma unroll
                for (int np = 0; np < 2; np++) LDSM_X4(Bl[np], bLo + np * 16 * XSTRB + kb);
                #pragma unroll
                for (int mt = 0; mt < 4; mt++)
                    #pragma unroll
                    for (int nt = 0; nt < 4; nt++)
                        MMA16816(acc2[mt][nt], Ah[mt], Bl[nt >> 1][nt & 1], Bl[nt >> 1][2 + (nt & 1)]);
            }
        }
        CP_WAIT0();
        __syncthreads();
    }

    // ================= Epilogue2: stage O = acc2 + b2 =================
    float* Outs = (float*)(smem + SM_OUTS);   // [128][132] fp32
    {
        const int qr = lane >> 2;
        const int qc = (lane & 3) * 2;
        #pragma unroll
        for (int mt = 0; mt < 4; mt++) {
            const int r0 = m0 + mt * 16 + qr;
            #pragma unroll
            for (int nt = 0; nt < 4; nt++) {
                const int cc = n0b + nt * 8 + qc;
                float2 bb = *(const float2*)(b2 + cc);
                float2 o01 = make_float2(acc2[mt][nt][0] + bb.x, acc2[mt][nt][1] + bb.y);
                float2 o23 = make_float2(acc2[mt][nt][2] + bb.x, acc2[mt][nt][3] + bb.y);
                *(float2*)(Outs + (size_t)r0 * 132 + cc)       = o01;
                *(float2*)(Outs + (size_t)(r0 + 8) * 132 + cc) = o23;
            }
        }
    }
    __syncthreads();

    // ================= LayerNorm + store (warp per row) =================
    for (int row = wid; row < BM; row += 8) {
        float4 v = *(const float4*)(Outs + (size_t)row * 132 + lane * 4);
        float s = v.x + v.y + v.z + v.w;
        float q = v.x * v.x + v.y * v.y + v.z * v.z + v.w * v.w;
        #pragma unroll
        for (int o = 16; o > 0; o >>= 1) {
            s += __shfl_xor_sync(0xFFFFFFFFu, s, o);
            q += __shfl_xor_sync(0xFFFFFFFFu, q, o);
        }
        float mu  = s * (1.f / 128.f);
        float var = q * (1.f / 128.f) - mu * mu;
        float rs  = rsqrtf(var + 1e-5f);
        float4 g  = *(const float4*)(gamma_ + lane * 4);
        float4 be = *(const float4*)(beta_  + lane * 4);
        float4 o4;
        o4.x = (v.x - mu) * rs * g.x + be.x;
        o4.y = (v.y - mu) * rs * g.y + be.y;
        o4.z = (v.z - mu) * rs * g.z + be.z;
        o4.w = (v.w - mu) * rs * g.w + be.w;
        if (e0 + row < NEDGE)
            *(float4*)(out + (size_t)(e0 + row) * 128 + lane * 4) = o4;
    }
}

extern "C" void kernel_launch(void* const* d_in, const int* in_sizes, int n_in,
                              void* d_out, int out_size)
{
    const float* node_attr = (const float*)d_in[0];
    const float* edge_attr = (const float*)d_in[1];
    const int*   eidx      = (const int*)  d_in[2];
    const float* W1        = (const float*)d_in[3];
    const float* b1        = (const float*)d_in[4];
    const float* W2        = (const float*)d_in[5];
    const float* b2        = (const float*)d_in[6];
    const float* gamma_    = (const float*)d_in[7];
    const float* beta_     = (const float*)d_in[8];
    float*       out       = (float*)d_out;

    prep_weights<<<(384 * 256 + 255) / 256, 256>>>(W1, W2);

    cudaFuncSetAttribute(edge_mlp_mma,
                         cudaFuncAttributeMaxDynamicSharedMemorySize, SM_TOTAL);
    int grid = (NEDGE + BM - 1) / BM;   // 2344
    edge_mlp_mma<<<grid, NT, SM_TOTAL>>>(
        node_attr, edge_attr, eidx, b1, b2, gamma_, beta_, out);
}

// round 7
// speedup vs baseline: 2.9536x; 1.1352x over previous
#include <cuda_runtime.h>
#include <cuda_bf16.h>
#include <cstdint>

#define NEDGE  300000
#define DNODE  128
#define NT     512
#define BM     128

#define XSTRB  144          // bytes per bf16 row (72 bf16 = 64 data + 8 pad)

// ---- smem byte offsets ----
#define SM_XBUF   0
#define SM_XSTRIDE 36864
#define SM_XLO_OFF 18432
#define SM_W1BUF  73728
#define SM_W1STRIDE 73728
#define SM_W1LO_OFF 36864
#define SM_W2BUF  0
#define SM_W2STRIDE 36864
#define SM_W2LO_OFF 18432
#define SM_HHI    73728
#define SM_HLO    147456
#define SM_HSTRIDE 18432
#define SM_OUTS   0
#define SM_TOTAL  221184

__device__ __align__(16) unsigned short g_W1t_hi[6 * 256 * 72];
__device__ __align__(16) unsigned short g_W1t_lo[6 * 256 * 72];
__device__ __align__(16) unsigned short g_W2t_hi[4 * 128 * 72];
__device__ __align__(16) unsigned short g_W2t_lo[4 * 128 * 72];

__device__ __forceinline__ uint32_t smem_u32(const void* p) {
    uint32_t a;
    asm("{ .reg .u64 t; cvta.to.shared.u64 t, %1; cvt.u32.u64 %0, t; }" : "=r"(a) : "l"(p));
    return a;
}

#define LDSM_X4(r, a) \
    asm volatile("ldmatrix.sync.aligned.m8n8.x4.shared.b16 {%0,%1,%2,%3}, [%4];" \
        : "=r"((r)[0]), "=r"((r)[1]), "=r"((r)[2]), "=r"((r)[3]) : "r"(a))

#define MMA16816(d, a, b0r, b1r) \
    asm volatile("mma.sync.aligned.m16n8k16.row.col.f32.bf16.bf16.f32 " \
        "{%0,%1,%2,%3}, {%4,%5,%6,%7}, {%8,%9}, {%0,%1,%2,%3};" \
        : "+f"((d)[0]), "+f"((d)[1]), "+f"((d)[2]), "+f"((d)[3]) \
        : "r"((a)[0]), "r"((a)[1]), "r"((a)[2]), "r"((a)[3]), "r"(b0r), "r"(b1r))

#define CP16(dst, src) \
    asm volatile("cp.async.cg.shared.global [%0], [%1], 16;" :: "r"(dst), "l"(src) : "memory")
#define CP_COMMIT() asm volatile("cp.async.commit_group;" ::: "memory")
#define CP_WAIT0()  asm volatile("cp.async.wait_group 0;" ::: "memory")

__device__ __forceinline__ void split_pack8(const float* f, uint4* hi, uint4* lo) {
    unsigned short hs[8], ls[8];
    #pragma unroll
    for (int j = 0; j < 8; j++) {
        __nv_bfloat16 b = __float2bfloat16_rn(f[j]);
        float r = f[j] - __bfloat162float(b);
        hs[j] = __bfloat16_as_ushort(b);
        ls[j] = __bfloat16_as_ushort(__float2bfloat16_rn(r));
    }
    hi->x = (uint32_t)hs[0] | ((uint32_t)hs[1] << 16);
    hi->y = (uint32_t)hs[2] | ((uint32_t)hs[3] << 16);
    hi->z = (uint32_t)hs[4] | ((uint32_t)hs[5] << 16);
    hi->w = (uint32_t)hs[6] | ((uint32_t)hs[7] << 16);
    lo->x = (uint32_t)ls[0] | ((uint32_t)ls[1] << 16);
    lo->y = (uint32_t)ls[2] | ((uint32_t)ls[3] << 16);
    lo->z = (uint32_t)ls[4] | ((uint32_t)ls[5] << 16);
    lo->w = (uint32_t)ls[6] | ((uint32_t)ls[7] << 16);
}

__device__ __forceinline__ uint32_t pack_hi2(float v0, float v1, uint32_t* lo) {
    __nv_bfloat16 h0 = __float2bfloat16_rn(v0);
    __nv_bfloat16 h1 = __float2bfloat16_rn(v1);
    float r0 = v0 - __bfloat162float(h0);
    float r1 = v1 - __bfloat162float(h1);
    *lo = (uint32_t)__bfloat16_as_ushort(__float2bfloat16_rn(r0))
        | ((uint32_t)__bfloat16_as_ushort(__float2bfloat16_rn(r1)) << 16);
    return (uint32_t)__bfloat16_as_ushort(h0)
         | ((uint32_t)__bfloat16_as_ushort(h1) << 16);
}

__global__ void prep_weights(const float* __restrict__ W1, const float* __restrict__ W2) {
    int idx = blockIdx.x * blockDim.x + threadIdx.x;
    if (idx < 384 * 256) {
        int k = idx >> 8, n = idx & 255;
        float v = W1[idx];
        __nv_bfloat16 h = __float2bfloat16_rn(v);
        float r = v - __bfloat162float(h);
        int c = k >> 6, kin = k & 63;
        int o = (c * 256 + n) * 72 + kin;
        g_W1t_hi[o] = __bfloat16_as_ushort(h);
        g_W1t_lo[o] = __bfloat16_as_ushort(__float2bfloat16_rn(r));
    }
    if (idx < 256 * 128) {
        int k = idx >> 7, n = idx & 127;
        float v = W2[idx];
        __nv_bfloat16 h = __float2bfloat16_rn(v);
        float r = v - __bfloat162float(h);
        int c = k >> 6, kin = k & 63;
        int o = (c * 128 + n) * 72 + kin;
        g_W2t_hi[o] = __bfloat16_as_ushort(h);
        g_W2t_lo[o] = __bfloat16_as_ushort(__float2bfloat16_rn(r));
    }
}

__global__ void __launch_bounds__(NT, 1)
edge_mlp_mma(const float* __restrict__ node_attr,
             const float* __restrict__ edge_attr,
             const int*   __restrict__ eidx,
             const float* __restrict__ b1,
             const float* __restrict__ b2,
             const float* __restrict__ gamma_,
             const float* __restrict__ beta_,
             float*       __restrict__ out)
{
    extern __shared__ __align__(16) char smem[];
    const uint32_t sb = smem_u32(smem);

    const int tid  = threadIdx.x;
    const int lane = tid & 31;
    const int wid  = tid >> 5;          // 0..15
    const int e0   = blockIdx.x * BM;
    const int nrows = min(BM, NEDGE - e0);

    const int lr  = (lane & 7) + ((lane >> 3) & 1) * 8;
    const int lcb = (lane >> 4) * 16;

    const int m0 = (wid >> 2) * 32;     // 4 row groups of 32
    const int nw = (wid & 3);
    const int n0 = nw * 64;             // GEMM1 col group

    const int grow = tid >> 2;          // 0..127
    const int gq   = tid & 3;           // quarter of 64-elem chunk (16 elems)

    int sidx = 0, ridx = 0;
    const bool gvalid = (grow < nrows);
    if (gvalid) {
        sidx = __ldg(&eidx[e0 + grow]);
        ridx = __ldg(&eidx[NEDGE + e0 + grow]);
    }

    #define GATHER_X(c, xbase) do { \
        const float* _src = nullptr; \
        if (gvalid) { \
            if ((c) < 2)      _src = node_attr + (size_t)sidx * DNODE + (c) * 64; \
            else if ((c) < 4) _src = node_attr + (size_t)ridx * DNODE + ((c) - 2) * 64; \
            else              _src = edge_attr + (size_t)(e0 + grow) * DNODE + ((c) - 4) * 64; \
        } \
        _Pragma("unroll") \
        for (int _g = 0; _g < 2; _g++) { \
            float _f[8]; \
            if (_src) { \
                float4 _a4 = *(const float4*)(_src + gq * 16 + _g * 8); \
                float4 _b4 = *(const float4*)(_src + gq * 16 + _g * 8 + 4); \
                _f[0] = _a4.x; _f[1] = _a4.y; _f[2] = _a4.z; _f[3] = _a4.w; \
                _f[4] = _b4.x; _f[5] = _b4.y; _f[6] = _b4.z; _f[7] = _b4.w; \
            } else { \
                _Pragma("unroll") for (int _j = 0; _j < 8; _j++) _f[_j] = 0.f; \
            } \
            uint4 _hi, _lo; \
            split_pack8(_f, &_hi, &_lo); \
            uint32_t _off = (xbase) + grow * XSTRB + gq * 32 + _g * 16; \
            *(uint4*)(smem + _off)              = _hi; \
            *(uint4*)(smem + _off + SM_XLO_OFF) = _lo; \
        } \
    } while (0)

    #define CP_W1(c, wbase) do { \
        const char* _wh = (const char*)g_W1t_hi + (c) * 36864; \
        const char* _wl = (const char*)g_W1t_lo + (c) * 36864; \
        uint32_t _dh = sb + (wbase); \
        uint32_t _dl = sb + (wbase) + SM_W1LO_OFF; \
        _Pragma("unroll") \
        for (int _i = 0; _i < 5; _i++) { \
            int _idx = tid + _i * NT; \
            if (_idx < 2304) { \
                uint32_t _o = (uint32_t)_idx * 16; \
                CP16(_dh + _o, _wh + _o); \
                CP16(_dl + _o, _wl + _o); \
            } \
        } \
    } while (0)

    #define CP_W2(c, wbase) do { \
        const char* _wh = (const char*)g_W2t_hi + (c) * 18432; \
        const char* _wl = (const char*)g_W2t_lo + (c) * 18432; \
        uint32_t _dh = sb + (wbase); \
        uint32_t _dl = sb + (wbase) + SM_W2LO_OFF; \
        _Pragma("unroll") \
        for (int _i = 0; _i < 3; _i++) { \
            int _idx = tid + _i * NT; \
            if (_idx < 1152) { \
                uint32_t _o = (uint32_t)_idx * 16; \
                CP16(_dh + _o, _wh + _o); \
                CP16(_dl + _o, _wl + _o); \
            } \
        } \
    } while (0)

    // ================= GEMM1 (pipelined) =================
    float acc[2][8][4];
    #pragma unroll
    for (int a = 0; a < 2; a++)
        #pragma unroll
        for (int b = 0; b < 8; b++)
            #pragma unroll
            for (int j = 0; j < 4; j++) acc[a][b][j] = 0.f;

    CP_W1(0, SM_W1BUF);
    CP_COMMIT();
    GATHER_X(0, SM_XBUF);
    CP_WAIT0();
    __syncthreads();

    for (int c = 0; c < 6; c++) {
        const int nb = (c + 1) & 1;
        if (c < 5) {
            CP_W1(c + 1, SM_W1BUF + nb * SM_W1STRIDE);
            CP_COMMIT();
            GATHER_X(c + 1, SM_XBUF + nb * SM_XSTRIDE);
        } else {
            CP_W2(0, SM_W2BUF);
            CP_COMMIT();
        }

        const uint32_t xb = SM_XBUF + (uint32_t)(c & 1) * SM_XSTRIDE;
        const uint32_t wb = SM_W1BUF + (uint32_t)(c & 1) * SM_W1STRIDE;
        const uint32_t aHi = sb + xb + (uint32_t)(m0 + lr) * XSTRB + lcb;
        const uint32_t aLo = aHi + SM_XLO_OFF;
        const uint32_t bHi = sb + wb + (uint32_t)(n0 + lr) * XSTRB + lcb;
        const uint32_t bLo = bHi + SM_W1LO_OFF;

        #pragma unroll
        for (int ks = 0; ks < 4; ks++) {
            const int kb = ks * 32;
            uint32_t Ah[2][4], Bh[4][4];
            #pragma unroll
            for (int mt = 0; mt < 2; mt++) LDSM_X4(Ah[mt], aHi + mt * 16 * XSTRB + kb);
            #pragma unroll
            for (int np = 0; np < 4; np++) LDSM_X4(Bh[np], bHi + np * 16 * XSTRB + kb);
            #pragma unroll
            for (int mt = 0; mt < 2; mt++)
                #pragma unroll
                for (int nt = 0; nt < 8; nt++)
                    MMA16816(acc[mt][nt], Ah[mt], Bh[nt >> 1][nt & 1], Bh[nt >> 1][2 + (nt & 1)]);
            {
                uint32_t Al[2][4];
                #pragma unroll
                for (int mt = 0; mt < 2; mt++) LDSM_X4(Al[mt], aLo + mt * 16 * XSTRB + kb);
                #pragma unroll
                for (int mt = 0; mt < 2; mt++)
                    #pragma unroll
                    for (int nt = 0; nt < 8; nt++)
                        MMA16816(acc[mt][nt], Al[mt], Bh[nt >> 1][nt & 1], Bh[nt >> 1][2 + (nt & 1)]);
            }
            {
                uint32_t Bl[4][4];
                #pragma unroll
                for (int np = 0; np < 4; np++) LDSM_X4(Bl[np], bLo + np * 16 * XSTRB + kb);
                #pragma unroll
                for (int mt = 0; mt < 2; mt++)
                    #pragma unroll
                    for (int nt = 0; nt < 8; nt++)
                        MMA16816(acc[mt][nt], Ah[mt], Bl[nt >> 1][nt & 1], Bl[nt >> 1][2 + (nt & 1)]);
            }
        }
        CP_WAIT0();
        __syncthreads();
    }

    // ================= Epilogue1: H = relu(acc + b1) -> bf16 hi/lo chunks =================
    {
        const int qr = lane >> 2;
        const int qc = (lane & 3) * 2;
        #pragma unroll
        for (int mt = 0; mt < 2; mt++) {
            const int r0 = m0 + mt * 16 + qr;
            #pragma unroll
            for (int nt = 0; nt < 8; nt++) {
                const int kin = nt * 8 + qc;
                float2 bb = *(const float2*)(b1 + n0 + kin);
                float v0 = fmaxf(acc[mt][nt][0] + bb.x, 0.f);
                float v1 = fmaxf(acc[mt][nt][1] + bb.y, 0.f);
                float v2 = fmaxf(acc[mt][nt][2] + bb.x, 0.f);
                float v3 = fmaxf(acc[mt][nt][3] + bb.y, 0.f);
                uint32_t l01, l23;
                uint32_t h01 = pack_hi2(v0, v1, &l01);
                uint32_t h23 = pack_hi2(v2, v3, &l23);
                uint32_t boff = (uint32_t)nw * SM_HSTRIDE + (uint32_t)r0 * XSTRB + kin * 2;
                *(uint32_t*)(smem + SM_HHI + boff)             = h01;
                *(uint32_t*)(smem + SM_HLO + boff)             = l01;
                *(uint32_t*)(smem + SM_HHI + boff + 8 * XSTRB) = h23;
                *(uint32_t*)(smem + SM_HLO + boff + 8 * XSTRB) = l23;
            }
        }
    }
    __syncthreads();

    // ================= GEMM2 (pipelined) =================
    const int n0b = (wid & 3) * 32;
    float acc2[2][4][4];
    #pragma unroll
    for (int a = 0; a < 2; a++)
        #pragma unroll
        for (int b = 0; b < 4; b++)
            #pragma unroll
            for (int j = 0; j < 4; j++) acc2[a][b][j] = 0.f;

    for (int c = 0; c < 4; c++) {
        const int nb = (c + 1) & 1;
        if (c < 3) {
            CP_W2(c + 1, SM_W2BUF + nb * SM_W2STRIDE);
            CP_COMMIT();
        }

        const uint32_t aHi = sb + SM_HHI + (uint32_t)c * SM_HSTRIDE + (uint32_t)(m0 + lr) * XSTRB + lcb;
        const uint32_t aLo = sb + SM_HLO + (uint32_t)c * SM_HSTRIDE + (uint32_t)(m0 + lr) * XSTRB + lcb;
        const uint32_t bHi = sb + SM_W2BUF + (uint32_t)(c & 1) * SM_W2STRIDE + (uint32_t)(n0b + lr) * XSTRB + lcb;
        const uint32_t bLo = bHi + SM_W2LO_OFF;

        #pragma unroll
        for (int ks = 0; ks < 4; ks++) {
            const int kb = ks * 32;
            uint32_t Ah[2][4], Bh[2][4];
            #pragma unroll
            for (int mt = 0; mt < 2; mt++) LDSM_X4(Ah[mt], aHi + mt * 16 * XSTRB + kb);
            #pragma unroll
            for (int np = 0; np < 2; np++) LDSM_X4(Bh[np], bHi + np * 16 * XSTRB + kb);
            #pragma unroll
            for (int mt = 0; mt < 2; mt++)
                #pragma unroll
                for (int nt = 0; nt < 4; nt++)
                    MMA16816(acc2[mt][nt], Ah[mt], Bh[nt >> 1][nt & 1], Bh[nt >> 1][2 + (nt & 1)]);
            {
                uint32_t Al[2][4];
                #pragma unroll
                for (int mt = 0; mt < 2; mt++) LDSM_X4(Al[mt], aLo + mt * 16 * XSTRB + kb);
                #pragma unroll
                for (int mt = 0; mt < 2; mt++)
                    #pragma unroll
                    for (int nt = 0; nt < 4; nt++)
                        MMA16816(acc2[mt][nt], Al[mt], Bh[nt >> 1][nt & 1], Bh[nt >> 1][2 + (nt & 1)]);
            }
            {
                uint32_t Bl[2][4];
                #pragma unroll
                for (int np = 0; np < 2; np++) LDSM_X4(Bl[np], bLo + np * 16 * XSTRB + kb);
                #pragma unroll
                for (int mt = 0; mt < 2; mt++)
                    #pragma unroll
                    for (int nt = 0; nt < 4; nt++)
                        MMA16816(acc2[mt][nt], Ah[mt], Bl[nt >> 1][nt & 1], Bl[nt >> 1][2 + (nt & 1)]);
            }
        }
        CP_WAIT0();
        __syncthreads();
    }

    // ================= Epilogue2: stage O = acc2 + b2 =================
    float* Outs = (float*)(smem + SM_OUTS);   // [128][132] fp32
    {
        const int qr = lane >> 2;
        const int qc = (lane & 3) * 2;
        #pragma unroll
        for (int mt = 0; mt < 2; mt++) {
            const int r0 = m0 + mt * 16 + qr;
            #pragma unroll
            for (int nt = 0; nt < 4; nt++) {
                const int cc = n0b + nt * 8 + qc;
                float2 bb = *(const float2*)(b2 + cc);
                float2 o01 = make_float2(acc2[mt][nt][0] + bb.x, acc2[mt][nt][1] + bb.y);
                float2 o23 = make_float2(acc2[mt][nt][2] + bb.x, acc2[mt][nt][3] + bb.y);
                *(float2*)(Outs + (size_t)r0 * 132 + cc)       = o01;
                *(float2*)(Outs + (size_t)(r0 + 8) * 132 + cc) = o23;
            }
        }
    }
    __syncthreads();

    // ================= LayerNorm + store (warp per row) =================
    for (int row = wid; row < BM; row += 16) {
        float4 v = *(const float4*)(Outs + (size_t)row * 132 + lane * 4);
        float s = v.x + v.y + v.z + v.w;
        float q = v.x * v.x + v.y * v.y + v.z * v.z + v.w * v.w;
        #pragma unroll
        for (int o = 16; o > 0; o >>= 1) {
            s += __shfl_xor_sync(0xFFFFFFFFu, s, o);
            q += __shfl_xor_sync(0xFFFFFFFFu, q, o);
        }
        float mu  = s * (1.f / 128.f);
        float var = q * (1.f / 128.f) - mu * mu;
        float rs  = rsqrtf(var + 1e-5f);
        float4 g  = *(const float4*)(gamma_ + lane * 4);
        float4 be = *(const float4*)(beta_  + lane * 4);
        float4 o4;
        o4.x = (v.x - mu) * rs * g.x + be.x;
        o4.y = (v.y - mu) * rs * g.y + be.y;
        o4.z = (v.z - mu) * rs * g.z + be.z;
        o4.w = (v.w - mu) * rs * g.w + be.w;
        if (e0 + row < NEDGE)
            *(float4*)(out + (size_t)(e0 + row) * 128 + lane * 4) = o4;
    }
}

extern "C" void kernel_launch(void* const* d_in, const int* in_sizes, int n_in,
                              void* d_out, int out_size)
{
    const float* node_attr = (const float*)d_in[0];
    const float* edge_attr = (const float*)d_in[1];
    const int*   eidx      = (const int*)  d_in[2];
    const float* W1        = (const float*)d_in[3];
    const float* b1        = (const float*)d_in[4];
    const float* W2        = (const float*)d_in[5];
    const float* b2        = (const float*)d_in[6];
    const float* gamma_    = (const float*)d_in[7];
    const float* beta_     = (const float*)d_in[8];
    float*       out       = (float*)d_out;

    prep_weights<<<(384 * 256 + 255) / 256, 256>>>(W1, W2);

    cudaFuncSetAttribute(edge_mlp_mma,
                         cudaFuncAttributeMaxDynamicSharedMemorySize, SM_TOTAL);
    int grid = (NEDGE + BM - 1) / BM;   // 2344
    edge_mlp_mma<<<grid, NT, SM_TOTAL>>>(
        node_attr, edge_attr, eidx, b1, b2, gamma_, beta_, out);
}

// round 11
// speedup vs baseline: 4.3203x; 1.4627x over previous
#include <cuda_runtime.h>
#include <cuda_fp16.h>
#include <cstdint>

#define NEDGE  300000
#define DNODE  128
#define NT     512
#define BM     128

#define XSTRB  144          // bytes per fp16 row (72 halves = 64 data + 8 pad)

// ---- smem byte offsets (identical to round-7 known-good layout) ----
#define SM_XBUF   0
#define SM_XSTRIDE 36864
#define SM_XLO_OFF 18432
#define SM_W1BUF  73728
#define SM_W1STRIDE 73728
#define SM_W1LO_OFF 36864
#define SM_W2BUF  0
#define SM_W2STRIDE 36864
#define SM_W2LO_OFF 18432
#define SM_HHI    73728
#define SM_HSTRIDE 18432
#define SM_OUTS   0
#define SM_TOTAL  221184

__device__ __align__(16) unsigned short g_W1t_hi[6 * 256 * 72];
__device__ __align__(16) unsigned short g_W1t_lo[6 * 256 * 72];
__device__ __align__(16) unsigned short g_W2t_hi[4 * 128 * 72];
__device__ __align__(16) unsigned short g_W2t_lo[4 * 128 * 72];

__device__ __forceinline__ uint32_t smem_u32(const void* p) {
    uint32_t a;
    asm("{ .reg .u64 t; cvta.to.shared.u64 t, %1; cvt.u32.u64 %0, t; }" : "=r"(a) : "l"(p));
    return a;
}

#define LDSM_X4(r, a) \
    asm volatile("ldmatrix.sync.aligned.m8n8.x4.shared.b16 {%0,%1,%2,%3}, [%4];" \
        : "=r"((r)[0]), "=r"((r)[1]), "=r"((r)[2]), "=r"((r)[3]) : "r"(a))

#define MMA16816(d, a, b0r, b1r) \
    asm volatile("mma.sync.aligned.m16n8k16.row.col.f32.f16.f16.f32 " \
        "{%0,%1,%2,%3}, {%4,%5,%6,%7}, {%8,%9}, {%0,%1,%2,%3};" \
        : "+f"((d)[0]), "+f"((d)[1]), "+f"((d)[2]), "+f"((d)[3]) \
        : "r"((a)[0]), "r"((a)[1]), "r"((a)[2]), "r"((a)[3]), "r"(b0r), "r"(b1r))

#define CP16(dst, src) \
    asm volatile("cp.async.cg.shared.global [%0], [%1], 16;" :: "r"(dst), "l"(src) : "memory")
#define CP_COMMIT() asm volatile("cp.async.commit_group;" ::: "memory")
#define CP_WAIT0()  asm volatile("cp.async.wait_group 0;" ::: "memory")

__device__ __forceinline__ uint32_t pack_h2(float a, float b) {
    __half2 t = __floats2half2_rn(a, b);
    return *reinterpret_cast<uint32_t*>(&t);
}

__device__ __forceinline__ uint4 pack8h(const float* f) {
    uint4 u;
    u.x = pack_h2(f[0], f[1]);
    u.y = pack_h2(f[2], f[3]);
    u.z = pack_h2(f[4], f[5]);
    u.w = pack_h2(f[6], f[7]);
    return u;
}

__global__ void prep_weights(const float* __restrict__ W1, const float* __restrict__ W2) {
    int idx = blockIdx.x * blockDim.x + threadIdx.x;
    if (idx < 384 * 256) {
        int k = idx >> 8, n = idx & 255;
        float v = W1[idx];
        __half h = __float2half_rn(v);
        float r = v - __half2float(h);
        __half l = __float2half_rn(r);
        int c = k >> 6, kin = k & 63;
        int o = (c * 256 + n) * 72 + kin;
        g_W1t_hi[o] = *reinterpret_cast<unsigned short*>(&h);
        g_W1t_lo[o] = *reinterpret_cast<unsigned short*>(&l);
    }
    if (idx < 256 * 128) {
        int k = idx >> 7, n = idx & 127;
        float v = W2[idx];
        __half h = __float2half_rn(v);
        float r = v - __half2float(h);
        __half l = __float2half_rn(r);
        int c = k >> 6, kin = k & 63;
        int o = (c * 128 + n) * 72 + kin;
        g_W2t_hi[o] = *reinterpret_cast<unsigned short*>(&h);
        g_W2t_lo[o] = *reinterpret_cast<unsigned short*>(&l);
    }
}

__global__ void __launch_bounds__(NT, 1)
edge_mlp_mma(const float* __restrict__ node_attr,
             const float* __restrict__ edge_attr,
             const int*   __restrict__ eidx,
             const float* __restrict__ b1,
             const float* __restrict__ b2,
             const float* __restrict__ gamma_,
             const float* __restrict__ beta_,
             float*       __restrict__ out)
{
    extern __shared__ __align__(16) char smem[];
    const uint32_t sb = smem_u32(smem);

    const int tid  = threadIdx.x;
    const int lane = tid & 31;
    const int wid  = tid >> 5;          // 0..15
    const int e0   = blockIdx.x * BM;
    const int nrows = min(BM, NEDGE - e0);

    const int lr  = (lane & 7) + ((lane >> 3) & 1) * 8;
    const int lcb = (lane >> 4) * 16;

    const int m0 = (wid >> 2) * 32;     // 4 row groups of 32
    const int nw = (wid & 3);
    const int n0 = nw * 64;             // GEMM1 col group

    const int grow = tid >> 2;          // 0..127
    const int gq   = tid & 3;           // quarter (16 elems)

    int sidx = 0, ridx = 0;
    const bool gvalid = (grow < nrows);
    if (gvalid) {
        sidx = __ldg(&eidx[e0 + grow]);
        ridx = __ldg(&eidx[NEDGE + e0 + grow]);
    }

    #define GATHER_X(c, xbase) do { \
        const float* _src = nullptr; \
        if (gvalid) { \
            if ((c) < 2)      _src = node_attr + (size_t)sidx * DNODE + (c) * 64; \
            else if ((c) < 4) _src = node_attr + (size_t)ridx * DNODE + ((c) - 2) * 64; \
            else              _src = edge_attr + (size_t)(e0 + grow) * DNODE + ((c) - 4) * 64; \
        } \
        _Pragma("unroll") \
        for (int _g = 0; _g < 2; _g++) { \
            float _f[8]; \
            if (_src) { \
                float4 _a4 = *(const float4*)(_src + gq * 16 + _g * 8); \
                float4 _b4 = *(const float4*)(_src + gq * 16 + _g * 8 + 4); \
                _f[0] = _a4.x; _f[1] = _a4.y; _f[2] = _a4.z; _f[3] = _a4.w; \
                _f[4] = _b4.x; _f[5] = _b4.y; _f[6] = _b4.z; _f[7] = _b4.w; \
            } else { \
                _Pragma("unroll") for (int _j = 0; _j < 8; _j++) _f[_j] = 0.f; \
            } \
            uint32_t _off = (xbase) + grow * XSTRB + gq * 32 + _g * 16; \
            *(uint4*)(smem + _off) = pack8h(_f); \
        } \
    } while (0)

    #define CP_W1(c, wbase) do { \
        const char* _wh = (const char*)g_W1t_hi + (c) * 36864; \
        const char* _wl = (const char*)g_W1t_lo + (c) * 36864; \
        uint32_t _dh = sb + (wbase); \
        uint32_t _dl = sb + (wbase) + SM_W1LO_OFF; \
        _Pragma("unroll") \
        for (int _i = 0; _i < 5; _i++) { \
            int _idx = tid + _i * NT; \
            if (_idx < 2304) { \
                uint32_t _o = (uint32_t)_idx * 16; \
                CP16(_dh + _o, _wh + _o); \
                CP16(_dl + _o, _wl + _o); \
            } \
        } \
    } while (0)

    #define CP_W2(c, wbase) do { \
        const char* _wh = (const char*)g_W2t_hi + (c) * 18432; \
        const char* _wl = (const char*)g_W2t_lo + (c) * 18432; \
        uint32_t _dh = sb + (wbase); \
        uint32_t _dl = sb + (wbase) + SM_W2LO_OFF; \
        _Pragma("unroll") \
        for (int _i = 0; _i < 3; _i++) { \
            int _idx = tid + _i * NT; \
            if (_idx < 1152) { \
                uint32_t _o = (uint32_t)_idx * 16; \
                CP16(_dh + _o, _wh + _o); \
                CP16(_dl + _o, _wl + _o); \
            } \
        } \
    } while (0)

    // ================= GEMM1 (pipelined) =================
    float acc[2][8][4];
    #pragma unroll
    for (int a = 0; a < 2; a++)
        #pragma unroll
        for (int b = 0; b < 8; b++)
            #pragma unroll
            for (int j = 0; j < 4; j++) acc[a][b][j] = 0.f;

    CP_W1(0, SM_W1BUF);
    CP_COMMIT();
    GATHER_X(0, SM_XBUF);
    CP_WAIT0();
    __syncthreads();

    for (int c = 0; c < 6; c++) {
        const int nb = (c + 1) & 1;
        if (c < 5) {
            CP_W1(c + 1, SM_W1BUF + nb * SM_W1STRIDE);
            CP_COMMIT();
            GATHER_X(c + 1, SM_XBUF + nb * SM_XSTRIDE);
        } else {
            CP_W2(0, SM_W2BUF);   // prefetch W2 chunk 0 into free Xbuf0 region (round-7 scheme)
            CP_COMMIT();
        }

        const uint32_t xb = SM_XBUF + (uint32_t)(c & 1) * SM_XSTRIDE;
        const uint32_t wb = SM_W1BUF + (uint32_t)(c & 1) * SM_W1STRIDE;
        const uint32_t aAd = sb + xb + (uint32_t)(m0 + lr) * XSTRB + lcb;
        const uint32_t bHi = sb + wb + (uint32_t)(n0 + lr) * XSTRB + lcb;
        const uint32_t bLo = bHi + SM_W1LO_OFF;

        #pragma unroll
        for (int ks = 0; ks < 4; ks++) {
            const int kb = ks * 32;
            uint32_t Ah[2][4], Bh[4][4], Bl[4][4];
            #pragma unroll
            for (int mt = 0; mt < 2; mt++) LDSM_X4(Ah[mt], aAd + mt * 16 * XSTRB + kb);
            #pragma unroll
            for (int np = 0; np < 4; np++) LDSM_X4(Bh[np], bHi + np * 16 * XSTRB + kb);
            #pragma unroll
            for (int np = 0; np < 4; np++) LDSM_X4(Bl[np], bLo + np * 16 * XSTRB + kb);
            #pragma unroll
            for (int mt = 0; mt < 2; mt++)
                #pragma unroll
                for (int nt = 0; nt < 8; nt++)
                    MMA16816(acc[mt][nt], Ah[mt], Bh[nt >> 1][nt & 1], Bh[nt >> 1][2 + (nt & 1)]);
            #pragma unroll
            for (int mt = 0; mt < 2; mt++)
                #pragma unroll
                for (int nt = 0; nt < 8; nt++)
                    MMA16816(acc[mt][nt], Ah[mt], Bl[nt >> 1][nt & 1], Bl[nt >> 1][2 + (nt & 1)]);
        }
        CP_WAIT0();
        __syncthreads();
    }

    // ================= Epilogue1: H = relu(acc + b1) -> fp16 chunks =================
    {
        const int qr = lane >> 2;
        const int qc = (lane & 3) * 2;
        #pragma unroll
        for (int mt = 0; mt < 2; mt++) {
            const int r0 = m0 + mt * 16 + qr;
            #pragma unroll
            for (int nt = 0; nt < 8; nt++) {
                const int kin = nt * 8 + qc;
                float2 bb = *(const float2*)(b1 + n0 + kin);
                float v0 = fmaxf(acc[mt][nt][0] + bb.x, 0.f);
                float v1 = fmaxf(acc[mt][nt][1] + bb.y, 0.f);
                float v2 = fmaxf(acc[mt][nt][2] + bb.x, 0.f);
                float v3 = fmaxf(acc[mt][nt][3] + bb.y, 0.f);
                uint32_t boff = SM_HHI + (uint32_t)nw * SM_HSTRIDE + (uint32_t)r0 * XSTRB + kin * 2;
                *(uint32_t*)(smem + boff)             = pack_h2(v0, v1);
                *(uint32_t*)(smem + boff + 8 * XSTRB) = pack_h2(v2, v3);
            }
        }
    }
    __syncthreads();

    // ================= GEMM2 (pipelined) =================
    const int n0b = (wid & 3) * 32;
    float acc2[2][4][4];
    #pragma unroll
    for (int a = 0; a < 2; a++)
        #pragma unroll
        for (int b = 0; b < 4; b++)
            #pragma unroll
            for (int j = 0; j < 4; j++) acc2[a][b][j] = 0.f;

    for (int c = 0; c < 4; c++) {
        const int nb = (c + 1) & 1;
        if (c < 3) {
            CP_W2(c + 1, SM_W2BUF + nb * SM_W2STRIDE);
            CP_COMMIT();
        }

        const uint32_t aAd = sb + SM_HHI + (uint32_t)c * SM_HSTRIDE + (uint32_t)(m0 + lr) * XSTRB + lcb;
        const uint32_t bHi = sb + SM_W2BUF + (uint32_t)(c & 1) * SM_W2STRIDE + (uint32_t)(n0b + lr) * XSTRB + lcb;
        const uint32_t bLo = bHi + SM_W2LO_OFF;

        #pragma unroll
        for (int ks = 0; ks < 4; ks++) {
            const int kb = ks * 32;
            uint32_t Ah[2][4], Bh[2][4], Bl[2][4];
            #pragma unroll
            for (int mt = 0; mt < 2; mt++) LDSM_X4(Ah[mt], aAd + mt * 16 * XSTRB + kb);
            #pragma unroll
            for (int np = 0; np < 2; np++) LDSM_X4(Bh[np], bHi + np * 16 * XSTRB + kb);
            #pragma unroll
            for (int np = 0; np < 2; np++) LDSM_X4(Bl[np], bLo + np * 16 * XSTRB + kb);
            #pragma unroll
            for (int mt = 0; mt < 2; mt++)
                #pragma unroll
                for (int nt = 0; nt < 4; nt++)
                    MMA16816(acc2[mt][nt], Ah[mt], Bh[nt >> 1][nt & 1], Bh[nt >> 1][2 + (nt & 1)]);
            #pragma unroll
            for (int mt = 0; mt < 2; mt++)
                #pragma unroll
                for (int nt = 0; nt < 4; nt++)
                    MMA16816(acc2[mt][nt], Ah[mt], Bl[nt >> 1][nt & 1], Bl[nt >> 1][2 + (nt & 1)]);
        }
        CP_WAIT0();
        __syncthreads();
    }

    // ================= Epilogue2: stage O = acc2 + b2 =================
    float* Outs = (float*)(smem + SM_OUTS);   // [128][132] fp32
    {
        const int qr = lane >> 2;
        const int qc = (lane & 3) * 2;
        #pragma unroll
        for (int mt = 0; mt < 2; mt++) {
            const int r0 = m0 + mt * 16 + qr;
            #pragma unroll
            for (int nt = 0; nt < 4; nt++) {
                const int cc = n0b + nt * 8 + qc;
                float2 bb = *(const float2*)(b2 + cc);
                float2 o01 = make_float2(acc2[mt][nt][0] + bb.x, acc2[mt][nt][1] + bb.y);
                float2 o23 = make_float2(acc2[mt][nt][2] + bb.x, acc2[mt][nt][3] + bb.y);
                *(float2*)(Outs + (size_t)r0 * 132 + cc)       = o01;
                *(float2*)(Outs + (size_t)(r0 + 8) * 132 + cc) = o23;
            }
        }
    }
    __syncthreads();

    // ================= LayerNorm + store (warp per row) =================
    for (int row = wid; row < BM; row += 16) {
        float4 v = *(const float4*)(Outs + (size_t)row * 132 + lane * 4);
        float s = v.x + v.y + v.z + v.w;
        float q = v.x * v.x + v.y * v.y + v.z * v.z + v.w * v.w;
        #pragma unroll
        for (int o = 16; o > 0; o >>= 1) {
            s += __shfl_xor_sync(0xFFFFFFFFu, s, o);
            q += __shfl_xor_sync(0xFFFFFFFFu, q, o);
        }
        float mu  = s * (1.f / 128.f);
        float var = q * (1.f / 128.f) - mu * mu;
        float rs  = rsqrtf(var + 1e-5f);
        float4 g  = *(const float4*)(gamma_ + lane * 4);
        float4 be = *(const float4*)(beta_  + lane * 4);
        float4 o4;
        o4.x = (v.x - mu) * rs * g.x + be.x;
        o4.y = (v.y - mu) * rs * g.y + be.y;
        o4.z = (v.z - mu) * rs * g.z + be.z;
        o4.w = (v.w - mu) * rs * g.w + be.w;
        if (e0 + row < NEDGE)
            *(float4*)(out + (size_t)(e0 + row) * 128 + lane * 4) = o4;
    }
}

extern "C" void kernel_launch(void* const* d_in, const int* in_sizes, int n_in,
                              void* d_out, int out_size)
{
    const float* node_attr = (const float*)d_in[0];
    const float* edge_attr = (const float*)d_in[1];
    const int*   eidx      = (const int*)  d_in[2];
    const float* W1        = (const float*)d_in[3];
    const float* b1        = (const float*)d_in[4];
    const float* W2        = (const float*)d_in[5];
    const float* b2        = (const float*)d_in[6];
    const float* gamma_    = (const float*)d_in[7];
    const float* beta_     = (const float*)d_in[8];
    float*       out       = (float*)d_out;

    prep_weights<<<(384 * 256 + 255) / 256, 256>>>(W1, W2);

    cudaFuncSetAttribute(edge_mlp_mma,
                         cudaFuncAttributeMaxDynamicSharedMemorySize, SM_TOTAL);
    int grid = (NEDGE + BM - 1) / BM;   // 2344
    edge_mlp_mma<<<grid, NT, SM_TOTAL>>>(
        node_attr, edge_attr, eidx, b1, b2, gamma_, beta_, out);
}

// round 14
// speedup vs baseline: 5.6185x; 1.3005x over previous
#include <cuda_runtime.h>
#include <cuda_fp16.h>
#include <cstdint>

#define NEDGE  300000
#define DNODE  128
#define NT     512
#define BM     128

#define XSTRB  144          // bytes per fp16 row (72 halves = 64 data + 8 pad)

// ---- smem byte offsets (round-7/11 known-good layout; W1-lo region unused) ----
#define SM_XBUF   0
#define SM_XSTRIDE 36864
#define SM_XLO_OFF 18432
#define SM_W1BUF  73728
#define SM_W1STRIDE 73728
#define SM_W1LO_OFF 36864
#define SM_W2BUF  0
#define SM_W2STRIDE 36864
#define SM_W2LO_OFF 18432
#define SM_HHI    73728
#define SM_HSTRIDE 18432
#define SM_OUTS   0
#define SM_TOTAL  221184

__device__ __align__(16) unsigned short g_W1t_hi[6 * 256 * 72];
__device__ __align__(16) unsigned short g_W2t_hi[4 * 128 * 72];
__device__ __align__(16) unsigned short g_W2t_lo[4 * 128 * 72];

__device__ __forceinline__ uint32_t smem_u32(const void* p) {
    uint32_t a;
    asm("{ .reg .u64 t; cvta.to.shared.u64 t, %1; cvt.u32.u64 %0, t; }" : "=r"(a) : "l"(p));
    return a;
}

#define LDSM_X4(r, a) \
    asm volatile("ldmatrix.sync.aligned.m8n8.x4.shared.b16 {%0,%1,%2,%3}, [%4];" \
        : "=r"((r)[0]), "=r"((r)[1]), "=r"((r)[2]), "=r"((r)[3]) : "r"(a))

#define MMA16816(d, a, b0r, b1r) \
    asm volatile("mma.sync.aligned.m16n8k16.row.col.f32.f16.f16.f32 " \
        "{%0,%1,%2,%3}, {%4,%5,%6,%7}, {%8,%9}, {%0,%1,%2,%3};" \
        : "+f"((d)[0]), "+f"((d)[1]), "+f"((d)[2]), "+f"((d)[3]) \
        : "r"((a)[0]), "r"((a)[1]), "r"((a)[2]), "r"((a)[3]), "r"(b0r), "r"(b1r))

#define CP16(dst, src) \
    asm volatile("cp.async.cg.shared.global [%0], [%1], 16;" :: "r"(dst), "l"(src) : "memory")
#define CP_COMMIT() asm volatile("cp.async.commit_group;" ::: "memory")
#define CP_WAIT0()  asm volatile("cp.async.wait_group 0;" ::: "memory")

__device__ __forceinline__ uint32_t pack_h2(float a, float b) {
    __half2 t = __floats2half2_rn(a, b);
    return *reinterpret_cast<uint32_t*>(&t);
}

__device__ __forceinline__ uint4 pack8h(const float* f) {
    uint4 u;
    u.x = pack_h2(f[0], f[1]);
    u.y = pack_h2(f[2], f[3]);
    u.z = pack_h2(f[4], f[5]);
    u.w = pack_h2(f[6], f[7]);
    return u;
}

__global__ void prep_weights(const float* __restrict__ W1, const float* __restrict__ W2) {
    int idx = blockIdx.x * blockDim.x + threadIdx.x;
    if (idx < 384 * 256) {
        int k = idx >> 8, n = idx & 255;
        float v = W1[idx];
        __half h = __float2half_rn(v);
        int c = k >> 6, kin = k & 63;
        int o = (c * 256 + n) * 72 + kin;
        g_W1t_hi[o] = *reinterpret_cast<unsigned short*>(&h);
    }
    if (idx < 256 * 128) {
        int k = idx >> 7, n = idx & 127;
        float v = W2[idx];
        __half h = __float2half_rn(v);
        float r = v - __half2float(h);
        __half l = __float2half_rn(r);
        int c = k >> 6, kin = k & 63;
        int o = (c * 128 + n) * 72 + kin;
        g_W2t_hi[o] = *reinterpret_cast<unsigned short*>(&h);
        g_W2t_lo[o] = *reinterpret_cast<unsigned short*>(&l);
    }
}

__global__ void __launch_bounds__(NT, 1)
edge_mlp_mma(const float* __restrict__ node_attr,
             const float* __restrict__ edge_attr,
             const int*   __restrict__ eidx,
             const float* __restrict__ b1,
             const float* __restrict__ b2,
             const float* __restrict__ gamma_,
             const float* __restrict__ beta_,
             float*       __restrict__ out)
{
    extern __shared__ __align__(16) char smem[];
    const uint32_t sb = smem_u32(smem);

    const int tid  = threadIdx.x;
    const int lane = tid & 31;
    const int wid  = tid >> 5;          // 0..15
    const int e0   = blockIdx.x * BM;
    const int nrows = min(BM, NEDGE - e0);

    const int lr  = (lane & 7) + ((lane >> 3) & 1) * 8;
    const int lcb = (lane >> 4) * 16;

    const int m0 = (wid >> 2) * 32;     // 4 row groups of 32
    const int nw = (wid & 3);
    const int n0 = nw * 64;             // GEMM1 col group

    const int grow = tid >> 2;          // 0..127
    const int gq   = tid & 3;           // quarter (16 elems)

    int sidx = 0, ridx = 0;
    const bool gvalid = (grow < nrows);
    if (gvalid) {
        sidx = __ldg(&eidx[e0 + grow]);
        ridx = __ldg(&eidx[NEDGE + e0 + grow]);
    }

    #define GATHER_X(c, xbase) do { \
        const float* _src = nullptr; \
        if (gvalid) { \
            if ((c) < 2)      _src = node_attr + (size_t)sidx * DNODE + (c) * 64; \
            else if ((c) < 4) _src = node_attr + (size_t)ridx * DNODE + ((c) - 2) * 64; \
            else              _src = edge_attr + (size_t)(e0 + grow) * DNODE + ((c) - 4) * 64; \
        } \
        _Pragma("unroll") \
        for (int _g = 0; _g < 2; _g++) { \
            float _f[8]; \
            if (_src) { \
                float4 _a4 = *(const float4*)(_src + gq * 16 + _g * 8); \
                float4 _b4 = *(const float4*)(_src + gq * 16 + _g * 8 + 4); \
                _f[0] = _a4.x; _f[1] = _a4.y; _f[2] = _a4.z; _f[3] = _a4.w; \
                _f[4] = _b4.x; _f[5] = _b4.y; _f[6] = _b4.z; _f[7] = _b4.w; \
            } else { \
                _Pragma("unroll") for (int _j = 0; _j < 8; _j++) _f[_j] = 0.f; \
            } \
            uint32_t _off = (xbase) + grow * XSTRB + gq * 32 + _g * 16; \
            *(uint4*)(smem + _off) = pack8h(_f); \
        } \
    } while (0)

    #define CP_W1(c, wbase) do { \
        const char* _wh = (const char*)g_W1t_hi + (c) * 36864; \
        uint32_t _dh = sb + (wbase); \
        _Pragma("unroll") \
        for (int _i = 0; _i < 5; _i++) { \
            int _idx = tid + _i * NT; \
            if (_idx < 2304) { \
                uint32_t _o = (uint32_t)_idx * 16; \
                CP16(_dh + _o, _wh + _o); \
            } \
        } \
    } while (0)

    #define CP_W2(c, wbase) do { \
        const char* _wh = (const char*)g_W2t_hi + (c) * 18432; \
        const char* _wl = (const char*)g_W2t_lo + (c) * 18432; \
        uint32_t _dh = sb + (wbase); \
        uint32_t _dl = sb + (wbase) + SM_W2LO_OFF; \
        _Pragma("unroll") \
        for (int _i = 0; _i < 3; _i++) { \
            int _idx = tid + _i * NT; \
            if (_idx < 1152) { \
                uint32_t _o = (uint32_t)_idx * 16; \
                CP16(_dh + _o, _wh + _o); \
                CP16(_dl + _o, _wl + _o); \
            } \
        } \
    } while (0)

    // ================= GEMM1 (pipelined, W1 hi-only) =================
    float acc[2][8][4];
    #pragma unroll
    for (int a = 0; a < 2; a++)
        #pragma unroll
        for (int b = 0; b < 8; b++)
            #pragma unroll
            for (int j = 0; j < 4; j++) acc[a][b][j] = 0.f;

    CP_W1(0, SM_W1BUF);
    CP_COMMIT();
    GATHER_X(0, SM_XBUF);
    CP_WAIT0();
    __syncthreads();

    for (int c = 0; c < 6; c++) {
        const int nb = (c + 1) & 1;
        if (c < 5) {
            CP_W1(c + 1, SM_W1BUF + nb * SM_W1STRIDE);
            CP_COMMIT();
            GATHER_X(c + 1, SM_XBUF + nb * SM_XSTRIDE);
        } else {
            CP_W2(0, SM_W2BUF);   // prefetch W2 chunk 0 into free Xbuf0 region (round-7 scheme)
            CP_COMMIT();
        }

        const uint32_t xb = SM_XBUF + (uint32_t)(c & 1) * SM_XSTRIDE;
        const uint32_t wb = SM_W1BUF + (uint32_t)(c & 1) * SM_W1STRIDE;
        const uint32_t aAd = sb + xb + (uint32_t)(m0 + lr) * XSTRB + lcb;
        const uint32_t bHi = sb + wb + (uint32_t)(n0 + lr) * XSTRB + lcb;

        #pragma unroll
        for (int ks = 0; ks < 4; ks++) {
            const int kb = ks * 32;
            uint32_t Ah[2][4], Bh[4][4];
            #pragma unroll
            for (int mt = 0; mt < 2; mt++) LDSM_X4(Ah[mt], aAd + mt * 16 * XSTRB + kb);
            #pragma unroll
            for (int np = 0; np < 4; np++) LDSM_X4(Bh[np], bHi + np * 16 * XSTRB + kb);
            #pragma unroll
            for (int mt = 0; mt < 2; mt++)
                #pragma unroll
                for (int nt = 0; nt < 8; nt++)
                    MMA16816(acc[mt][nt], Ah[mt], Bh[nt >> 1][nt & 1], Bh[nt >> 1][2 + (nt & 1)]);
        }
        CP_WAIT0();
        __syncthreads();
    }

    // ================= Epilogue1: H = relu(acc + b1) -> fp16 chunks =================
    {
        const int qr = lane >> 2;
        const int qc = (lane & 3) * 2;
        #pragma unroll
        for (int mt = 0; mt < 2; mt++) {
            const int r0 = m0 + mt * 16 + qr;
            #pragma unroll
            for (int nt = 0; nt < 8; nt++) {
                const int kin = nt * 8 + qc;
                float2 bb = *(const float2*)(b1 + n0 + kin);
                float v0 = fmaxf(acc[mt][nt][0] + bb.x, 0.f);
                float v1 = fmaxf(acc[mt][nt][1] + bb.y, 0.f);
                float v2 = fmaxf(acc[mt][nt][2] + bb.x, 0.f);
                float v3 = fmaxf(acc[mt][nt][3] + bb.y, 0.f);
                uint32_t boff = SM_HHI + (uint32_t)nw * SM_HSTRIDE + (uint32_t)r0 * XSTRB + kin * 2;
                *(uint32_t*)(smem + boff)             = pack_h2(v0, v1);
                *(uint32_t*)(smem + boff + 8 * XSTRB) = pack_h2(v2, v3);
            }
        }
    }
    __syncthreads();

    // ================= GEMM2 (pipelined, W2 hi+lo 2-pass) =================
    const int n0b = (wid & 3) * 32;
    float acc2[2][4][4];
    #pragma unroll
    for (int a = 0; a < 2; a++)
        #pragma unroll
        for (int b = 0; b < 4; b++)
            #pragma unroll
            for (int j = 0; j < 4; j++) acc2[a][b][j] = 0.f;

    for (int c = 0; c < 4; c++) {
        const int nb = (c + 1) & 1;
        if (c < 3) {
            CP_W2(c + 1, SM_W2BUF + nb * SM_W2STRIDE);
            CP_COMMIT();
        }

        const uint32_t aAd = sb + SM_HHI + (uint32_t)c * SM_HSTRIDE + (uint32_t)(m0 + lr) * XSTRB + lcb;
        const uint32_t bHi = sb + SM_W2BUF + (uint32_t)(c & 1) * SM_W2STRIDE + (uint32_t)(n0b + lr) * XSTRB + lcb;
        const uint32_t bLo = bHi + SM_W2LO_OFF;

        #pragma unroll
        for (int ks = 0; ks < 4; ks++) {
            const int kb = ks * 32;
            uint32_t Ah[2][4], Bh[2][4], Bl[2][4];
            #pragma unroll
            for (int mt = 0; mt < 2; mt++) LDSM_X4(Ah[mt], aAd + mt * 16 * XSTRB + kb);
            #pragma unroll
            for (int np = 0; np < 2; np++) LDSM_X4(Bh[np], bHi + np * 16 * XSTRB + kb);
            #pragma unroll
            for (int np = 0; np < 2; np++) LDSM_X4(Bl[np], bLo + np * 16 * XSTRB + kb);
            #pragma unroll
            for (int mt = 0; mt < 2; mt++)
                #pragma unroll
                for (int nt = 0; nt < 4; nt++)
                    MMA16816(acc2[mt][nt], Ah[mt], Bh[nt >> 1][nt & 1], Bh[nt >> 1][2 + (nt & 1)]);
            #pragma unroll
            for (int mt = 0; mt < 2; mt++)
                #pragma unroll
                for (int nt = 0; nt < 4; nt++)
                    MMA16816(acc2[mt][nt], Ah[mt], Bl[nt >> 1][nt & 1], Bl[nt >> 1][2 + (nt & 1)]);
        }
        CP_WAIT0();
        __syncthreads();
    }

    // ================= Epilogue2: stage O = acc2 + b2 =================
    float* Outs = (float*)(smem + SM_OUTS);   // [128][132] fp32
    {
        const int qr = lane >> 2;
        const int qc = (lane & 3) * 2;
        #pragma unroll
        for (int mt = 0; mt < 2; mt++) {
            const int r0 = m0 + mt * 16 + qr;
            #pragma unroll
            for (int nt = 0; nt < 4; nt++) {
                const int cc = n0b + nt * 8 + qc;
                float2 bb = *(const float2*)(b2 + cc);
                float2 o01 = make_float2(acc2[mt][nt][0] + bb.x, acc2[mt][nt][1] + bb.y);
                float2 o23 = make_float2(acc2[mt][nt][2] + bb.x, acc2[mt][nt][3] + bb.y);
                *(float2*)(Outs + (size_t)r0 * 132 + cc)       = o01;
                *(float2*)(Outs + (size_t)(r0 + 8) * 132 + cc) = o23;
            }
        }
    }
    __syncthreads();

    // ================= LayerNorm + store (warp per row) =================
    for (int row = wid; row < BM; row += 16) {
        float4 v = *(const float4*)(Outs + (size_t)row * 132 + lane * 4);
        float s = v.x + v.y + v.z + v.w;
        float q = v.x * v.x + v.y * v.y + v.z * v.z + v.w * v.w;
        #pragma unroll
        for (int o = 16; o > 0; o >>= 1) {
            s += __shfl_xor_sync(0xFFFFFFFFu, s, o);
            q += __shfl_xor_sync(0xFFFFFFFFu, q, o);
        }
        float mu  = s * (1.f / 128.f);
        float var = q * (1.f / 128.f) - mu * mu;
        float rs  = rsqrtf(var + 1e-5f);
        float4 g  = *(const float4*)(gamma_ + lane * 4);
        float4 be = *(const float4*)(beta_  + lane * 4);
        float4 o4;
        o4.x = (v.x - mu) * rs * g.x + be.x;
        o4.y = (v.y - mu) * rs * g.y + be.y;
        o4.z = (v.z - mu) * rs * g.z + be.z;
        o4.w = (v.w - mu) * rs * g.w + be.w;
        if (e0 + row < NEDGE)
            *(float4*)(out + (size_t)(e0 + row) * 128 + lane * 4) = o4;
    }
}

extern "C" void kernel_launch(void* const* d_in, const int* in_sizes, int n_in,
                              void* d_out, int out_size)
{
    const float* node_attr = (const float*)d_in[0];
    const float* edge_attr = (const float*)d_in[1];
    const int*   eidx      = (const int*)  d_in[2];
    const float* W1        = (const float*)d_in[3];
    const float* b1        = (const float*)d_in[4];
    const float* W2        = (const float*)d_in[5];
    const float* b2        = (const float*)d_in[6];
    const float* gamma_    = (const float*)d_in[7];
    const float* beta_     = (const float*)d_in[8];
    float*       out       = (float*)d_out;

    prep_weights<<<(384 * 256 + 255) / 256, 256>>>(W1, W2);

    cudaFuncSetAttribute(edge_mlp_mma,
                         cudaFuncAttributeMaxDynamicSharedMemorySize, SM_TOTAL);
    int grid = (NEDGE + BM - 1) / BM;   // 2344
    edge_mlp_mma<<<grid, NT, SM_TOTAL>>>(
        node_attr, edge_attr, eidx, b1, b2, gamma_, beta_, out);
}

// round 15
// speedup vs baseline: 6.3145x; 1.1239x over previous
#include <cuda_runtime.h>
#include <cuda_fp16.h>
#include <cstdint>

#define NEDGE  300000
#define DNODE  128
#define NT     512
#define BM     128

#define XSTRB  144          // bytes per fp16 row (72 halves = 64 data + 8 pad)

// ---- smem byte offsets ----
// GEMM1: Xbuf[2] @ 0/18432, W1buf[2] @ 36864/73728 (hi-only, compact stride)
//        W2 (full 4 chunks, hi-only) @ 110592..184320, loaded during c==5
// GEMM2: H chunks @ 0 (+c*18432, overlays Xbuf+W1buf), W2 resident @ 110592
// LN:    Outs fp32 [128][132] @ 0 (after post-GEMM2 barrier)
#define SM_XBUF     0
#define SM_XSTRIDE  18432
#define SM_W1BUF    36864
#define SM_W1STRIDE 36864
#define SM_W2BUF    110592
#define SM_W2CH     18432
#define SM_H        0
#define SM_HSTRIDE  18432
#define SM_OUTS     0
#define SM_TOTAL    221184   // keep known-good allocation size

__device__ __align__(16) unsigned short g_W1t_hi[6 * 256 * 72];
__device__ __align__(16) unsigned short g_W2t_hi[4 * 128 * 72];

__device__ __forceinline__ uint32_t smem_u32(const void* p) {
    uint32_t a;
    asm("{ .reg .u64 t; cvta.to.shared.u64 t, %1; cvt.u32.u64 %0, t; }" : "=r"(a) : "l"(p));
    return a;
}

#define LDSM_X4(r, a) \
    asm volatile("ldmatrix.sync.aligned.m8n8.x4.shared.b16 {%0,%1,%2,%3}, [%4];" \
        : "=r"((r)[0]), "=r"((r)[1]), "=r"((r)[2]), "=r"((r)[3]) : "r"(a))

#define MMA16816(d, a, b0r, b1r) \
    asm volatile("mma.sync.aligned.m16n8k16.row.col.f32.f16.f16.f32 " \
        "{%0,%1,%2,%3}, {%4,%5,%6,%7}, {%8,%9}, {%0,%1,%2,%3};" \
        : "+f"((d)[0]), "+f"((d)[1]), "+f"((d)[2]), "+f"((d)[3]) \
        : "r"((a)[0]), "r"((a)[1]), "r"((a)[2]), "r"((a)[3]), "r"(b0r), "r"(b1r))

#define CP16(dst, src) \
    asm volatile("cp.async.cg.shared.global [%0], [%1], 16;" :: "r"(dst), "l"(src) : "memory")
#define CP_COMMIT() asm volatile("cp.async.commit_group;" ::: "memory")
#define CP_WAIT0()  asm volatile("cp.async.wait_group 0;" ::: "memory")

__device__ __forceinline__ uint32_t pack_h2(float a, float b) {
    __half2 t = __floats2half2_rn(a, b);
    return *reinterpret_cast<uint32_t*>(&t);
}

__device__ __forceinline__ uint4 pack8h(const float* f) {
    uint4 u;
    u.x = pack_h2(f[0], f[1]);
    u.y = pack_h2(f[2], f[3]);
    u.z = pack_h2(f[4], f[5]);
    u.w = pack_h2(f[6], f[7]);
    return u;
}

__global__ void prep_weights(const float* __restrict__ W1, const float* __restrict__ W2) {
    int idx = blockIdx.x * blockDim.x + threadIdx.x;
    if (idx < 384 * 256) {
        int k = idx >> 8, n = idx & 255;
        float v = W1[idx];
        __half h = __float2half_rn(v);
        int c = k >> 6, kin = k & 63;
        int o = (c * 256 + n) * 72 + kin;
        g_W1t_hi[o] = *reinterpret_cast<unsigned short*>(&h);
    }
    if (idx < 256 * 128) {
        int k = idx >> 7, n = idx & 127;
        float v = W2[idx];
        __half h = __float2half_rn(v);
        int c = k >> 6, kin = k & 63;
        int o = (c * 128 + n) * 72 + kin;
        g_W2t_hi[o] = *reinterpret_cast<unsigned short*>(&h);
    }
}

__global__ void __launch_bounds__(NT, 1)
edge_mlp_mma(const float* __restrict__ node_attr,
             const float* __restrict__ edge_attr,
             const int*   __restrict__ eidx,
             const float* __restrict__ b1,
             const float* __restrict__ b2,
             const float* __restrict__ gamma_,
             const float* __restrict__ beta_,
             float*       __restrict__ out)
{
    extern __shared__ __align__(16) char smem[];
    const uint32_t sb = smem_u32(smem);

    const int tid  = threadIdx.x;
    const int lane = tid & 31;
    const int wid  = tid >> 5;          // 0..15
    const int e0   = blockIdx.x * BM;
    const int nrows = min(BM, NEDGE - e0);

    const int lr  = (lane & 7) + ((lane >> 3) & 1) * 8;
    const int lcb = (lane >> 4) * 16;

    const int m0 = (wid >> 2) * 32;     // 4 row groups of 32
    const int nw = (wid & 3);
    const int n0 = nw * 64;             // GEMM1 col group

    const int grow = tid >> 2;          // 0..127
    const int gq   = tid & 3;           // quarter (16 elems)

    int sidx = 0, ridx = 0;
    const bool gvalid = (grow < nrows);
    if (gvalid) {
        sidx = __ldg(&eidx[e0 + grow]);
        ridx = __ldg(&eidx[NEDGE + e0 + grow]);
    }

    #define GATHER_X(c, xbase) do { \
        const float* _src = nullptr; \
        if (gvalid) { \
            if ((c) < 2)      _src = node_attr + (size_t)sidx * DNODE + (c) * 64; \
            else if ((c) < 4) _src = node_attr + (size_t)ridx * DNODE + ((c) - 2) * 64; \
            else              _src = edge_attr + (size_t)(e0 + grow) * DNODE + ((c) - 4) * 64; \
        } \
        _Pragma("unroll") \
        for (int _g = 0; _g < 2; _g++) { \
            float _f[8]; \
            if (_src) { \
                float4 _a4 = *(const float4*)(_src + gq * 16 + _g * 8); \
                float4 _b4 = *(const float4*)(_src + gq * 16 + _g * 8 + 4); \
                _f[0] = _a4.x; _f[1] = _a4.y; _f[2] = _a4.z; _f[3] = _a4.w; \
                _f[4] = _b4.x; _f[5] = _b4.y; _f[6] = _b4.z; _f[7] = _b4.w; \
            } else { \
                _Pragma("unroll") for (int _j = 0; _j < 8; _j++) _f[_j] = 0.f; \
            } \
            uint32_t _off = (xbase) + grow * XSTRB + gq * 32 + _g * 16; \
            *(uint4*)(smem + _off) = pack8h(_f); \
        } \
    } while (0)

    #define CP_W1(c, wbase) do { \
        const char* _wh = (const char*)g_W1t_hi + (c) * 36864; \
        uint32_t _dh = sb + (wbase); \
        _Pragma("unroll") \
        for (int _i = 0; _i < 5; _i++) { \
            int _idx = tid + _i * NT; \
            if (_idx < 2304) { \
                uint32_t _o = (uint32_t)_idx * 16; \
                CP16(_dh + _o, _wh + _o); \
            } \
        } \
    } while (0)

    // copy full W2 (hi-only, 4 chunks = 4608 uint4) to resident region
    #define CP_W2_ALL() do { \
        const char* _wh = (const char*)g_W2t_hi; \
        uint32_t _dh = sb + SM_W2BUF; \
        _Pragma("unroll") \
        for (int _i = 0; _i < 9; _i++) { \
            uint32_t _o = (uint32_t)(tid + _i * NT) * 16; \
            CP16(_dh + _o, _wh + _o); \
        } \
    } while (0)

    // ================= GEMM1 (pipelined, W1 hi-only) =================
    float acc[2][8][4];
    #pragma unroll
    for (int a = 0; a < 2; a++)
        #pragma unroll
        for (int b = 0; b < 8; b++)
            #pragma unroll
            for (int j = 0; j < 4; j++) acc[a][b][j] = 0.f;

    CP_W1(0, SM_W1BUF);
    CP_COMMIT();
    GATHER_X(0, SM_XBUF);
    CP_WAIT0();
    __syncthreads();

    for (int c = 0; c < 6; c++) {
        const int nb = (c + 1) & 1;
        if (c < 5) {
            CP_W1(c + 1, SM_W1BUF + nb * SM_W1STRIDE);
            CP_COMMIT();
            GATHER_X(c + 1, SM_XBUF + nb * SM_XSTRIDE);
        } else {
            CP_W2_ALL();          // resident W2 region, no overlay conflicts
            CP_COMMIT();
        }

        const uint32_t xb = SM_XBUF + (uint32_t)(c & 1) * SM_XSTRIDE;
        const uint32_t wb = SM_W1BUF + (uint32_t)(c & 1) * SM_W1STRIDE;
        const uint32_t aAd = sb + xb + (uint32_t)(m0 + lr) * XSTRB + lcb;
        const uint32_t bHi = sb + wb + (uint32_t)(n0 + lr) * XSTRB + lcb;

        #pragma unroll
        for (int ks = 0; ks < 4; ks++) {
            const int kb = ks * 32;
            uint32_t Ah[2][4], Bh[4][4];
            #pragma unroll
            for (int mt = 0; mt < 2; mt++) LDSM_X4(Ah[mt], aAd + mt * 16 * XSTRB + kb);
            #pragma unroll
            for (int np = 0; np < 4; np++) LDSM_X4(Bh[np], bHi + np * 16 * XSTRB + kb);
            #pragma unroll
            for (int mt = 0; mt < 2; mt++)
                #pragma unroll
                for (int nt = 0; nt < 8; nt++)
                    MMA16816(acc[mt][nt], Ah[mt], Bh[nt >> 1][nt & 1], Bh[nt >> 1][2 + (nt & 1)]);
        }
        CP_WAIT0();
        __syncthreads();
    }

    // ================= Epilogue1: H = relu(acc + b1) -> fp16 chunks @ SM_H =================
    {
        const int qr = lane >> 2;
        const int qc = (lane & 3) * 2;
        #pragma unroll
        for (int mt = 0; mt < 2; mt++) {
            const int r0 = m0 + mt * 16 + qr;
            #pragma unroll
            for (int nt = 0; nt < 8; nt++) {
                const int kin = nt * 8 + qc;
                float2 bb = *(const float2*)(b1 + n0 + kin);
                float v0 = fmaxf(acc[mt][nt][0] + bb.x, 0.f);
                float v1 = fmaxf(acc[mt][nt][1] + bb.y, 0.f);
                float v2 = fmaxf(acc[mt][nt][2] + bb.x, 0.f);
                float v3 = fmaxf(acc[mt][nt][3] + bb.y, 0.f);
                uint32_t boff = SM_H + (uint32_t)nw * SM_HSTRIDE + (uint32_t)r0 * XSTRB + kin * 2;
                *(uint32_t*)(smem + boff)             = pack_h2(v0, v1);
                *(uint32_t*)(smem + boff + 8 * XSTRB) = pack_h2(v2, v3);
            }
        }
    }
    __syncthreads();

    // ================= GEMM2 (W2 resident, barrier-free inner) =================
    const int n0b = (wid & 3) * 32;
    float acc2[2][4][4];
    #pragma unroll
    for (int a = 0; a < 2; a++)
        #pragma unroll
        for (int b = 0; b < 4; b++)
            #pragma unroll
            for (int j = 0; j < 4; j++) acc2[a][b][j] = 0.f;

    #pragma unroll
    for (int c = 0; c < 4; c++) {
        const uint32_t aAd = sb + SM_H + (uint32_t)c * SM_HSTRIDE + (uint32_t)(m0 + lr) * XSTRB + lcb;
        const uint32_t bHi = sb + SM_W2BUF + (uint32_t)c * SM_W2CH + (uint32_t)(n0b + lr) * XSTRB + lcb;

        #pragma unroll
        for (int ks = 0; ks < 4; ks++) {
            const int kb = ks * 32;
            uint32_t Ah[2][4], Bh[2][4];
            #pragma unroll
            for (int mt = 0; mt < 2; mt++) LDSM_X4(Ah[mt], aAd + mt * 16 * XSTRB + kb);
            #pragma unroll
            for (int np = 0; np < 2; np++) LDSM_X4(Bh[np], bHi + np * 16 * XSTRB + kb);
            #pragma unroll
            for (int mt = 0; mt < 2; mt++)
                #pragma unroll
                for (int nt = 0; nt < 4; nt++)
                    MMA16816(acc2[mt][nt], Ah[mt], Bh[nt >> 1][nt & 1], Bh[nt >> 1][2 + (nt & 1)]);
        }
    }
    __syncthreads();   // all H/W2 reads done; Outs overlays below

    // ================= Epilogue2: stage O = acc2 + b2 =================
    float* Outs = (float*)(smem + SM_OUTS);   // [128][132] fp32
    {
        const int qr = lane >> 2;
        const int qc = (lane & 3) * 2;
        #pragma unroll
        for (int mt = 0; mt < 2; mt++) {
            const int r0 = m0 + mt * 16 + qr;
            #pragma unroll
            for (int nt = 0; nt < 4; nt++) {
                const int cc = n0b + nt * 8 + qc;
                float2 bb = *(const float2*)(b2 + cc);
                float2 o01 = make_float2(acc2[mt][nt][0] + bb.x, acc2[mt][nt][1] + bb.y);
                float2 o23 = make_float2(acc2[mt][nt][2] + bb.x, acc2[mt][nt][3] + bb.y);
                *(float2*)(Outs + (size_t)r0 * 132 + cc)       = o01;
                *(float2*)(Outs + (size_t)(r0 + 8) * 132 + cc) = o23;
            }
        }
    }
    __syncthreads();

    // ================= LayerNorm + store (warp per row) =================
    for (int row = wid; row < BM; row += 16) {
        float4 v = *(const float4*)(Outs + (size_t)row * 132 + lane * 4);
        float s = v.x + v.y + v.z + v.w;
        float q = v.x * v.x + v.y * v.y + v.z * v.z + v.w * v.w;
        #pragma unroll
        for (int o = 16; o > 0; o >>= 1) {
            s += __shfl_xor_sync(0xFFFFFFFFu, s, o);
            q += __shfl_xor_sync(0xFFFFFFFFu, q, o);
        }
        float mu  = s * (1.f / 128.f);
        float var = q * (1.f / 128.f) - mu * mu;
        float rs  = rsqrtf(var + 1e-5f);
        float4 g  = *(const float4*)(gamma_ + lane * 4);
        float4 be = *(const float4*)(beta_  + lane * 4);
        float4 o4;
        o4.x = (v.x - mu) * rs * g.x + be.x;
        o4.y = (v.y - mu) * rs * g.y + be.y;
        o4.z = (v.z - mu) * rs * g.z + be.z;
        o4.w = (v.w - mu) * rs * g.w + be.w;
        if (e0 + row < NEDGE)
            *(float4*)(out + (size_t)(e0 + row) * 128 + lane * 4) = o4;
    }
}

extern "C" void kernel_launch(void* const* d_in, const int* in_sizes, int n_in,
                              void* d_out, int out_size)
{
    const float* node_attr = (const float*)d_in[0];
    const float* edge_attr = (const float*)d_in[1];
    const int*   eidx      = (const int*)  d_in[2];
    const float* W1        = (const float*)d_in[3];
    const float* b1        = (const float*)d_in[4];
    const float* W2        = (const float*)d_in[5];
    const float* b2        = (const float*)d_in[6];
    const float* gamma_    = (const float*)d_in[7];
    const float* beta_     = (const float*)d_in[8];
    float*       out       = (float*)d_out;

    prep_weights<<<(384 * 256 + 255) / 256, 256>>>(W1, W2);

    cudaFuncSetAttribute(edge_mlp_mma,
                         cudaFuncAttributeMaxDynamicSharedMemorySize, SM_TOTAL);
    int grid = (NEDGE + BM - 1) / BM;   // 2344
    edge_mlp_mma<<<grid, NT, SM_TOTAL>>>(
        node_attr, edge_attr, eidx, b1, b2, gamma_, beta_, out);
}

// round 16
// speedup vs baseline: 6.4750x; 1.0254x over previous
#include <cuda_runtime.h>
#include <cuda_fp16.h>
#include <cstdint>

#define NEDGE  300000
#define DNODE  128
#define NT     512
#define BM     128

#define XST2   272          // bytes per fp16 row (136 halves = 128 data + 8 pad)

// ---- smem byte offsets ----
// GEMM1: X0 @ 0, X1 @ 34816 (128 rows x 272B); W1_0 @ 69632, W1_1 @ 139264 (256 rows x 272B)
//        W2 resident @ 139264 (2 chunks x 34816, overlays W1_1 after its last use)
// GEMM2: H @ 0 (+c*34816, overlays X0/X1), W2 @ 139264
// LN:    Outs fp32 [128][132] @ 0
#define SM_X0    0
#define SM_X1    34816
#define SM_W1_0  69632
#define SM_W1_1  139264
#define SM_W2    139264
#define SM_HCH   34816
#define SM_OUTS  0
#define SM_TOTAL 208896

__device__ __align__(16) unsigned short g_W1t_hi[3 * 256 * 136];
__device__ __align__(16) unsigned short g_W2t_hi[2 * 128 * 136];
__device__ __align__(16) unsigned short g_node_h[50000 * 128];

__device__ __forceinline__ uint32_t smem_u32(const void* p) {
    uint32_t a;
    asm("{ .reg .u64 t; cvta.to.shared.u64 t, %1; cvt.u32.u64 %0, t; }" : "=r"(a) : "l"(p));
    return a;
}

#define LDSM_X4(r, a) \
    asm volatile("ldmatrix.sync.aligned.m8n8.x4.shared.b16 {%0,%1,%2,%3}, [%4];" \
        : "=r"((r)[0]), "=r"((r)[1]), "=r"((r)[2]), "=r"((r)[3]) : "r"(a))

#define MMA16816(d, a, b0r, b1r) \
    asm volatile("mma.sync.aligned.m16n8k16.row.col.f32.f16.f16.f32 " \
        "{%0,%1,%2,%3}, {%4,%5,%6,%7}, {%8,%9}, {%0,%1,%2,%3};" \
        : "+f"((d)[0]), "+f"((d)[1]), "+f"((d)[2]), "+f"((d)[3]) \
        : "r"((a)[0]), "r"((a)[1]), "r"((a)[2]), "r"((a)[3]), "r"(b0r), "r"(b1r))

#define CP16(dst, src) \
    asm volatile("cp.async.cg.shared.global [%0], [%1], 16;" :: "r"(dst), "l"(src) : "memory")
#define CP_COMMIT() asm volatile("cp.async.commit_group;" ::: "memory")
#define CP_WAIT0()  asm volatile("cp.async.wait_group 0;" ::: "memory")

__device__ __forceinline__ uint32_t pack_h2(float a, float b) {
    __half2 t = __floats2half2_rn(a, b);
    return *reinterpret_cast<uint32_t*>(&t);
}

__device__ __forceinline__ uint4 pack8h(const float* f) {
    uint4 u;
    u.x = pack_h2(f[0], f[1]);
    u.y = pack_h2(f[2], f[3]);
    u.z = pack_h2(f[4], f[5]);
    u.w = pack_h2(f[6], f[7]);
    return u;
}

// W1 transposed [N][K] fp16, chunked by K with CHUNK REORDER:
//   chunk 0 = edge rows (k 256..383), chunk 1 = sender (k 0..127), chunk 2 = receiver (k 128..255)
// W2 transposed [N][K] fp16, 2 chunks of K=128. Rows padded to 136 halves.
__global__ void prep_weights(const float* __restrict__ W1, const float* __restrict__ W2) {
    int idx = blockIdx.x * blockDim.x + threadIdx.x;
    if (idx < 384 * 256) {
        int k = idx >> 8, n = idx & 255;
        float v = W1[idx];
        __half h = __float2half_rn(v);
        int chunk, kin;
        if (k < 128)      { chunk = 1; kin = k; }
        else if (k < 256) { chunk = 2; kin = k - 128; }
        else              { chunk = 0; kin = k - 256; }
        g_W1t_hi[(chunk * 256 + n) * 136 + kin] = *reinterpret_cast<unsigned short*>(&h);
    }
    if (idx < 256 * 128) {
        int k = idx >> 7, n = idx & 127;
        float v = W2[idx];
        __half h = __float2half_rn(v);
        g_W2t_hi[(((k >> 7) * 128) + n) * 136 + (k & 127)] = *reinterpret_cast<unsigned short*>(&h);
    }
}

// node_attr fp32 -> fp16 table (8 halves per thread)
__global__ void prep_node(const float* __restrict__ node_attr) {
    int i = blockIdx.x * blockDim.x + threadIdx.x;
    if (i < 50000 * 16) {
        const float* s = node_attr + (size_t)i * 8;
        float f[8];
        float4 a = *(const float4*)(s);
        float4 b = *(const float4*)(s + 4);
        f[0] = a.x; f[1] = a.y; f[2] = a.z; f[3] = a.w;
        f[4] = b.x; f[5] = b.y; f[6] = b.z; f[7] = b.w;
        *(uint4*)(g_node_h + (size_t)i * 8) = pack8h(f);
    }
}

__global__ void __launch_bounds__(NT, 1)
edge_mlp_mma(const float* __restrict__ node_attr,
             const float* __restrict__ edge_attr,
             const int*   __restrict__ eidx,
             const float* __restrict__ b1,
             const float* __restrict__ b2,
             const float* __restrict__ gamma_,
             const float* __restrict__ beta_,
             float*       __restrict__ out)
{
    extern __shared__ __align__(16) char smem[];
    const uint32_t sb = smem_u32(smem);

    const int tid  = threadIdx.x;
    const int lane = tid & 31;
    const int wid  = tid >> 5;          // 0..15
    const int e0   = blockIdx.x * BM;
    const int nrows = min(BM, NEDGE - e0);

    const int lr  = (lane & 7) + ((lane >> 3) & 1) * 8;
    const int lcb = (lane >> 4) * 16;

    const int m0 = (wid >> 2) * 32;     // 4 row groups of 32
    const int nw = (wid & 3);
    const int n0 = nw * 64;             // GEMM1 col group (64 of 256)

    const int grow = tid >> 2;          // 0..127 (X row)
    const int gq   = tid & 3;           // quarter of 128-half row (64B)

    int sidx = 0, ridx = 0;
    const bool gvalid = (grow < nrows);
    if (gvalid) {
        sidx = __ldg(&eidx[e0 + grow]);
        ridx = __ldg(&eidx[NEDGE + e0 + grow]);
    }

    // edge gather (chunk 0): fp32 LDG + pack, prologue only
    #define GATHER_EDGE() do { \
        if (gvalid) { \
            const float* _src = edge_attr + (size_t)(e0 + grow) * 128 + gq * 32; \
            _Pragma("unroll") \
            for (int _g = 0; _g < 4; _g++) { \
                float _f[8]; \
                float4 _a4 = *(const float4*)(_src + _g * 8); \
                float4 _b4 = *(const float4*)(_src + _g * 8 + 4); \
                _f[0] = _a4.x; _f[1] = _a4.y; _f[2] = _a4.z; _f[3] = _a4.w; \
                _f[4] = _b4.x; _f[5] = _b4.y; _f[6] = _b4.z; _f[7] = _b4.w; \
                *(uint4*)(smem + SM_X0 + grow * XST2 + gq * 64 + _g * 16) = pack8h(_f); \
            } \
        } else { \
            _Pragma("unroll") \
            for (int _g = 0; _g < 4; _g++) \
                *(uint4*)(smem + SM_X0 + grow * XST2 + gq * 64 + _g * 16) = make_uint4(0, 0, 0, 0); \
        } \
    } while (0)

    // node gather via cp.async from fp16 table (full 256B row per X row)
    #define CP_X_NODE(nidx, xbase) do { \
        const char* _s = (const char*)g_node_h + (size_t)(nidx) * 256 + gq * 64; \
        uint32_t _d = sb + (xbase) + (uint32_t)grow * XST2 + gq * 64; \
        CP16(_d,      _s); \
        CP16(_d + 16, _s + 16); \
        CP16(_d + 32, _s + 32); \
        CP16(_d + 48, _s + 48); \
    } while (0)

    // W1 chunk: 69632 B = 4352 uint4
    #define CP_W1(c, wbase) do { \
        const char* _wh = (const char*)g_W1t_hi + (c) * 69632; \
        uint32_t _dh = sb + (wbase); \
        _Pragma("unroll") \
        for (int _i = 0; _i < 9; _i++) { \
            int _idx = tid + _i * NT; \
            if (_idx < 4352) { \
                uint32_t _o = (uint32_t)_idx * 16; \
                CP16(_dh + _o, _wh + _o); \
            } \
        } \
    } while (0)

    // full W2: 69632 B = 4352 uint4
    #define CP_W2_ALL() do { \
        const char* _wh = (const char*)g_W2t_hi; \
        uint32_t _dh = sb + SM_W2; \
        _Pragma("unroll") \
        for (int _i = 0; _i < 9; _i++) { \
            int _idx = tid + _i * NT; \
            if (_idx < 4352) { \
                uint32_t _o = (uint32_t)_idx * 16; \
                CP16(_dh + _o, _wh + _o); \
            } \
        } \
    } while (0)

    // one GEMM1 chunk: 8 k-steps of 16
    #define MMA_CHUNK1(xbase, wbase) do { \
        const uint32_t _aAd = sb + (xbase) + (uint32_t)(m0 + lr) * XST2 + lcb; \
        const uint32_t _bAd = sb + (wbase) + (uint32_t)(n0 + lr) * XST2 + lcb; \
        _Pragma("unroll") \
        for (int _ks = 0; _ks < 8; _ks++) { \
            const int _kb = _ks * 32; \
            uint32_t _Ah[2][4], _Bh[4][4]; \
            _Pragma("unroll") \
            for (int _mt = 0; _mt < 2; _mt++) LDSM_X4(_Ah[_mt], _aAd + _mt * 16 * XST2 + _kb); \
            _Pragma("unroll") \
            for (int _np = 0; _np < 4; _np++) LDSM_X4(_Bh[_np], _bAd + _np * 16 * XST2 + _kb); \
            _Pragma("unroll") \
            for (int _mt = 0; _mt < 2; _mt++) \
                _Pragma("unroll") \
                for (int _nt = 0; _nt < 8; _nt++) \
                    MMA16816(acc[_mt][_nt], _Ah[_mt], _Bh[_nt >> 1][_nt & 1], _Bh[_nt >> 1][2 + (_nt & 1)]); \
        } \
    } while (0)

    // ================= GEMM1: 3 chunks of K=128 =================
    float acc[2][8][4];
    #pragma unroll
    for (int a = 0; a < 2; a++)
        #pragma unroll
        for (int b = 0; b < 8; b++)
            #pragma unroll
            for (int j = 0; j < 4; j++) acc[a][b][j] = 0.f;

    // prologue: W1 chunk0 async + edge gather into X0
    CP_W1(0, SM_W1_0);
    CP_COMMIT();
    GATHER_EDGE();
    CP_WAIT0();
    __syncthreads();

    // chunk 0 (edge)
    CP_W1(1, SM_W1_1);
    CP_X_NODE(sidx, SM_X1);      // sender rows -> X1
    CP_COMMIT();
    MMA_CHUNK1(SM_X0, SM_W1_0);
    CP_WAIT0();
    __syncthreads();

    // chunk 1 (sender)
    CP_W1(2, SM_W1_0);
    CP_X_NODE(ridx, SM_X0);      // receiver rows -> X0
    CP_COMMIT();
    MMA_CHUNK1(SM_X1, SM_W1_1);
    CP_WAIT0();
    __syncthreads();

    // chunk 2 (receiver); prefetch resident W2 into W1_1 region
    CP_W2_ALL();
    CP_COMMIT();
    MMA_CHUNK1(SM_X0, SM_W1_0);
    CP_WAIT0();
    __syncthreads();

    // ================= Epilogue1: H = relu(acc + b1) -> fp16 @ 0 =================
    {
        const int qr = lane >> 2;
        const int qc = (lane & 3) * 2;
        #pragma unroll
        for (int mt = 0; mt < 2; mt++) {
            const int r0 = m0 + mt * 16 + qr;
            #pragma unroll
            for (int nt = 0; nt < 8; nt++) {
                const int col = n0 + nt * 8 + qc;
                float2 bb = *(const float2*)(b1 + col);
                float v0 = fmaxf(acc[mt][nt][0] + bb.x, 0.f);
                float v1 = fmaxf(acc[mt][nt][1] + bb.y, 0.f);
                float v2 = fmaxf(acc[mt][nt][2] + bb.x, 0.f);
                float v3 = fmaxf(acc[mt][nt][3] + bb.y, 0.f);
                uint32_t boff = (uint32_t)(col >> 7) * SM_HCH + (uint32_t)r0 * XST2 + (col & 127) * 2;
                *(uint32_t*)(smem + boff)              = pack_h2(v0, v1);
                *(uint32_t*)(smem + boff + 8 * XST2)   = pack_h2(v2, v3);
            }
        }
    }
    __syncthreads();

    // ================= GEMM2: 2 chunks, W2 resident, barrier-free =================
    const int n0b = (wid & 3) * 32;
    float acc2[2][4][4];
    #pragma unroll
    for (int a = 0; a < 2; a++)
        #pragma unroll
        for (int b = 0; b < 4; b++)
            #pragma unroll
            for (int j = 0; j < 4; j++) acc2[a][b][j] = 0.f;

    #pragma unroll
    for (int c = 0; c < 2; c++) {
        const uint32_t aAd = sb + (uint32_t)c * SM_HCH + (uint32_t)(m0 + lr) * XST2 + lcb;
        const uint32_t bAd = sb + SM_W2 + (uint32_t)c * SM_HCH + (uint32_t)(n0b + lr) * XST2 + lcb;
        #pragma unroll
        for (int ks = 0; ks < 8; ks++) {
            const int kb = ks * 32;
            uint32_t Ah[2][4], Bh[2][4];
            #pragma unroll
            for (int mt = 0; mt < 2; mt++) LDSM_X4(Ah[mt], aAd + mt * 16 * XST2 + kb);
            #pragma unroll
            for (int np = 0; np < 2; np++) LDSM_X4(Bh[np], bAd + np * 16 * XST2 + kb);
            #pragma unroll
            for (int mt = 0; mt < 2; mt++)
                #pragma unroll
                for (int nt = 0; nt < 4; nt++)
                    MMA16816(acc2[mt][nt], Ah[mt], Bh[nt >> 1][nt & 1], Bh[nt >> 1][2 + (nt & 1)]);
        }
    }
    __syncthreads();   // all H/W2 reads done; Outs overlays below

    // ================= Epilogue2: stage O = acc2 + b2 =================
    float* Outs = (float*)(smem + SM_OUTS);   // [128][132] fp32
    {
        const int qr = lane >> 2;
        const int qc = (lane & 3) * 2;
        #pragma unroll
        for (int mt = 0; mt < 2; mt++) {
            const int r0 = m0 + mt * 16 + qr;
            #pragma unroll
            for (int nt = 0; nt < 4; nt++) {
                const int cc = n0b + nt * 8 + qc;
                float2 bb = *(const float2*)(b2 + cc);
                float2 o01 = make_float2(acc2[mt][nt][0] + bb.x, acc2[mt][nt][1] + bb.y);
                float2 o23 = make_float2(acc2[mt][nt][2] + bb.x, acc2[mt][nt][3] + bb.y);
                *(float2*)(Outs + (size_t)r0 * 132 + cc)       = o01;
                *(float2*)(Outs + (size_t)(r0 + 8) * 132 + cc) = o23;
            }
        }
    }
    __syncthreads();

    // ================= LayerNorm + store (warp per row) =================
    for (int row = wid; row < BM; row += 16) {
        float4 v = *(const float4*)(Outs + (size_t)row * 132 + lane * 4);
        float s = v.x + v.y + v.z + v.w;
        float q = v.x * v.x + v.y * v.y + v.z * v.z + v.w * v.w;
        #pragma unroll
        for (int o = 16; o > 0; o >>= 1) {
            s += __shfl_xor_sync(0xFFFFFFFFu, s, o);
            q += __shfl_xor_sync(0xFFFFFFFFu, q, o);
        }
        float mu  = s * (1.f / 128.f);
        float var = q * (1.f / 128.f) - mu * mu;
        float rs  = rsqrtf(var + 1e-5f);
        float4 g  = *(const float4*)(gamma_ + lane * 4);
        float4 be = *(const float4*)(beta_  + lane * 4);
        float4 o4;
        o4.x = (v.x - mu) * rs * g.x + be.x;
        o4.y = (v.y - mu) * rs * g.y + be.y;
        o4.z = (v.z - mu) * rs * g.z + be.z;
        o4.w = (v.w - mu) * rs * g.w + be.w;
        if (e0 + row < NEDGE)
            *(float4*)(out + (size_t)(e0 + row) * 128 + lane * 4) = o4;
    }
}

extern "C" void kernel_launch(void* const* d_in, const int* in_sizes, int n_in,
                              void* d_out, int out_size)
{
    const float* node_attr = (const float*)d_in[0];
    const float* edge_attr = (const float*)d_in[1];
    const int*   eidx      = (const int*)  d_in[2];
    const float* W1        = (const float*)d_in[3];
    const float* b1        = (const float*)d_in[4];
    const float* W2        = (const float*)d_in[5];
    const float* b2        = (const float*)d_in[6];
    const float* gamma_    = (const float*)d_in[7];
    const float* beta_     = (const float*)d_in[8];
    float*       out       = (float*)d_out;

    prep_weights<<<(384 * 256 + 255) / 256, 256>>>(W1, W2);
    prep_node<<<(50000 * 16 + 255) / 256, 256>>>(node_attr);

    cudaFuncSetAttribute(edge_mlp_mma,
                         cudaFuncAttributeMaxDynamicSharedMemorySize, SM_TOTAL);
    int grid = (NEDGE + BM - 1) / BM;   // 2344
    edge_mlp_mma<<<grid, NT, SM_TOTAL>>>(
        node_attr, edge_attr, eidx, b1, b2, gamma_, beta_, out);
}